// round 4
// baseline (speedup 1.0000x reference)
#include <cuda_runtime.h>

#define BB 256   // B*H*W samples

// ---------------- scratch (__device__ globals; allocation-free) ----------------
__device__ float g_X0[25165824];   // layer input   (max 768*256*128)
__device__ float g_U [25165824];   // U / Z stack   (max 3072*8192)
__device__ float g_Y [12582912];   // conv output   (max 768*256*64)
__device__ float g_S3[12582912];   // skip s3 (768,256,64)
__device__ float g_S2[ 6291456];   // skip s2 (192,256,128)
__device__ float g_S1[ 3145728];   // skip s1 (48,256,256)
__device__ float g_F [  196608];   // final (768,256)
__device__ float g_P3[2359296], g_PT3[2359296];
__device__ float g_P2[ 147456], g_PT2[ 147456];
__device__ float g_P1[   9216], g_PT1[   9216];
__device__ float g_P0[    576];
__device__ float g_ST[    512];    // BN sums: [0..F) sum, [F..2F) sumsq

__host__ __device__ __forceinline__ int imin(int a,int b){return a<b?a:b;}
__host__ __device__ __forceinline__ int imax(int a,int b){return a>b?a:b;}

// ---------------- generic tiled SGEMM: C = alpha*A@B + beta*D ----------------
// AMODE 0: A[r*lda + k]
// AMODE 1: A[(k/fin)*strideK + r*fin + (k%fin)]   (encoder k-gather)
// SPLITK : gridDim.z K-slices, atomicAdd into pre-zeroed C (D ignored)
template<int AMODE, bool SPLITK>
__global__ void __launch_bounds__(256)
gemm_k(int M, int Nc, int K,
       const float* __restrict__ A, int lda,
       const float* __restrict__ B, int ldb,
       float* __restrict__ C, int ldc,
       const float* __restrict__ D, float alpha, float beta,
       int fin, int strideK)
{
    __shared__ float As[16][65];
    __shared__ float Bs[16][65];
    const int row0 = blockIdx.y << 6;
    const int col0 = blockIdx.x << 6;
    const int tid  = threadIdx.y * 16 + threadIdx.x;

    int kb = 0, ke = K;
    if (SPLITK) {
        int ks = (K + gridDim.z - 1) / gridDim.z;
        kb = blockIdx.z * ks;
        ke = imin(K, kb + ks);
        if (kb >= ke) return;
    }

    float acc[4][4] = {};

    for (int kt = kb; kt < ke; kt += 16) {
        #pragma unroll
        for (int l = 0; l < 4; l++) {
            int e = tid + (l << 8);
            int m = e >> 4, kk = e & 15;
            int gr = row0 + m, gk = kt + kk;
            float v = 0.f;
            if (gr < M && gk < ke) {
                int addr;
                if (AMODE == 0) addr = gr * lda + gk;
                else            addr = (gk / fin) * strideK + gr * fin + (gk % fin);
                v = A[addr];
            }
            As[kk][m] = v;
        }
        #pragma unroll
        for (int l = 0; l < 4; l++) {
            int e = tid + (l << 8);
            int kk = e >> 6, n = e & 63;
            int gk = kt + kk, gc = col0 + n;
            float v = 0.f;
            if (gk < ke && gc < Nc) v = B[gk * ldb + gc];
            Bs[kk][n] = v;
        }
        __syncthreads();
        #pragma unroll
        for (int kk = 0; kk < 16; kk++) {
            float ra[4], rb[4];
            #pragma unroll
            for (int i = 0; i < 4; i++) ra[i] = As[kk][(threadIdx.y << 2) + i];
            #pragma unroll
            for (int j = 0; j < 4; j++) rb[j] = Bs[kk][(threadIdx.x << 2) + j];
            #pragma unroll
            for (int i = 0; i < 4; i++)
                #pragma unroll
                for (int j = 0; j < 4; j++)
                    acc[i][j] += ra[i] * rb[j];
        }
        __syncthreads();
    }

    #pragma unroll
    for (int i = 0; i < 4; i++) {
        int gr = row0 + (threadIdx.y << 2) + i;
        if (gr >= M) continue;
        #pragma unroll
        for (int j = 0; j < 4; j++) {
            int gc = col0 + (threadIdx.x << 2) + j;
            if (gc >= Nc) continue;
            float v = alpha * acc[i][j];
            int addr = gr * ldc + gc;
            if (SPLITK) atomicAdd(&C[addr], v);
            else {
                if (D != nullptr) v += beta * D[addr];
                C[addr] = v;
            }
        }
    }
}

// ---------------- small kernels ----------------
__global__ void zero_k(float* p, int n) {
    int i = blockIdx.x * blockDim.x + threadIdx.x;
    if (i < n) p[i] = 0.f;
}

__global__ void initP_k(float* __restrict__ P, const float* __restrict__ L, int N, int NN) {
    int i = blockIdx.x * blockDim.x + threadIdx.x;
    if (i >= 2 * NN) return;
    if (i < NN) P[i] = ((i / N) == (i % N)) ? 1.f : 0.f;
    else        P[i] = L[i - NN];
}

// PT[n][k*N+m] = P[k][n][m]
__global__ void transP_k(const float* __restrict__ P, float* __restrict__ PT, int N, int NN) {
    int i = blockIdx.x * blockDim.x + threadIdx.x;
    if (i >= 4 * NN) return;
    int k = i / NN, r = i - k * NN;
    int n = r / N,  m = r - n * N;
    PT[(n * 4 + k) * N + m] = P[i];
}

// x (4,8,8*8,768) -> X0 (768, 256, 8)
__global__ void permute_in_k(const float* __restrict__ x, float* __restrict__ dst) {
    int i = blockIdx.x * blockDim.x + threadIdx.x;
    if (i >= 768 * 256 * 8) return;
    int n = i >> 11;
    int rem = i & 2047;
    int bb = rem >> 3;
    int c  = rem & 7;
    int b  = bb >> 6, hw = bb & 63;
    dst[i] = x[(((b * 8 + c) * 64) + hw) * 768 + n];
}

// F (768,256) -> out (256,768): out[bb*768+n] = F[n*256+bb]
__global__ void permute_out_k(const float* __restrict__ Fm, float* __restrict__ out) {
    int i = blockIdx.x * blockDim.x + threadIdx.x;
    if (i >= 196608) return;
    int bb = i / 768, n = i - bb * 768;
    out[i] = Fm[n * 256 + bb];
}

// healpix 4:1 max pool on (N, BB, F) node axis
__global__ void pool_k(const float* __restrict__ src, float* __restrict__ dst, int Np, int F) {
    int i = blockIdx.x * blockDim.x + threadIdx.x;
    int rowsz = BB * F;
    int tot = Np * rowsz;
    if (i >= tot) return;
    int n4 = i / rowsz, rem = i - n4 * rowsz;
    const float* s = src + (4 * n4) * rowsz + rem;
    float v = s[0];
    v = fmaxf(v, s[rowsz]);
    v = fmaxf(v, s[2 * rowsz]);
    v = fmaxf(v, s[3 * rowsz]);
    dst[i] = v;
}

// dst (N,BB,Fa+Fb) = concat(unpool(H (N/4,BB,Fa)), S (N,BB,Fb))
__global__ void concat_k(const float* __restrict__ H, const float* __restrict__ S,
                         float* __restrict__ dst, int N, int Fa, int Fb) {
    int Ft = Fa + Fb;
    int i = blockIdx.x * blockDim.x + threadIdx.x;
    int tot = N * BB * Ft;
    if (i >= tot) return;
    int n = i / (BB * Ft);
    int rem = i - n * (BB * Ft);
    int bb = rem / Ft;
    int f  = rem - bb * Ft;
    float v;
    if (f < Fa) v = H[((n >> 2) * BB + bb) * Fa + f];
    else        v = S[(n * BB + bb) * Fb + (f - Fa)];
    dst[i] = v;
}

// BN stats: blockDim = (F, 256/F); per-channel sum/sumsq with shared reduce + atomics
__global__ void bn_stats_k(const float* __restrict__ Y, int R, int F, float* __restrict__ ST) {
    __shared__ float ssum[256];
    __shared__ float ssq [256];
    int tx = threadIdx.x, ty = threadIdx.y;
    int tid = ty * F + tx;
    int rpb = (R + gridDim.x - 1) / gridDim.x;
    int r0 = blockIdx.x * rpb;
    int r1 = imin(R, r0 + rpb);
    float s = 0.f, q = 0.f;
    for (int r = r0 + ty; r < r1; r += blockDim.y) {
        float v = Y[r * F + tx];
        s += v; q += v * v;
    }
    ssum[tid] = s; ssq[tid] = q;
    __syncthreads();
    if (ty == 0) {
        for (int yy = 1; yy < blockDim.y; yy++) {
            s += ssum[yy * F + tx];
            q += ssq [yy * F + tx];
        }
        atomicAdd(&ST[tx], s);
        atomicAdd(&ST[F + tx], q);
    }
}

__global__ void bn_apply_k(const float* __restrict__ src, float* __restrict__ dst,
                           int R, int F, const float* __restrict__ ST,
                           const float* __restrict__ g, const float* __restrict__ b) {
    int i = blockIdx.x * blockDim.x + threadIdx.x;
    int tot = R * F;
    if (i >= tot) return;
    int f = i % F;
    float m = (float)R;
    float mu = ST[f] / m;
    float var = ST[F + f] / m - mu * mu;
    float v = (src[i] - mu) * rsqrtf(var + 1e-5f) * g[f] + b[f];
    dst[i] = v > 0.f ? v : 0.f;
}

// ---------------- host helpers ----------------
template<typename T> static float* sym(T& s) {
    void* p = nullptr;
    cudaGetSymbolAddress(&p, s);
    return (float*)p;
}

static void gemm(int M, int Nc, int K, const float* A, int lda, const float* B, int ldb,
                 float* C, int ldc, const float* D, float alpha, float beta) {
    dim3 g((Nc + 63) / 64, (M + 63) / 64, 1), b(16, 16);
    gemm_k<0, false><<<g, b>>>(M, Nc, K, A, lda, B, ldb, C, ldc, D, alpha, beta, 0, 0);
}

static void gemm_gather(int M, int Nc, int Fin, const float* U, int strideK,
                        const float* B, float* C) {
    int K = 4 * Fin;
    dim3 g((Nc + 63) / 64, (M + 63) / 64, 1), b(16, 16);
    gemm_k<1, false><<<g, b>>>(M, Nc, K, U, 0, B, Nc, C, Nc, nullptr, 1.f, 0.f, Fin, strideK);
}

static void gemm_splitk(int M, int Nc, int K, const float* A, int lda, const float* B, int ldb,
                        float* C, int ldc, int slices) {
    dim3 g((Nc + 63) / 64, (M + 63) / 64, slices), b(16, 16);
    gemm_k<0, true><<<g, b>>>(M, Nc, K, A, lda, B, ldb, C, ldc, nullptr, 1.f, 0.f, 0, 0);
}

static void buildP(const float* L, int N, float* P, float* PT) {
    int NN = N * N;
    initP_k<<<(2 * NN + 255) / 256, 256>>>(P, L, N, NN);
    gemm(N, N, N, L, N, P + NN,     N, P + 2 * NN, N, P,      2.f, -1.f);
    gemm(N, N, N, L, N, P + 2 * NN, N, P + 3 * NN, N, P + NN, 2.f, -1.f);
    if (PT) transP_k<<<(4 * NN + 255) / 256, 256>>>(P, PT, N, NN);
}

// encoder order: U = Pstack @ X ; Y = gather_k(U) @ w
static void enc_layer(const float* X, int N, int Fin, int Fout, const float* Pst,
                      const float* w, float* U, float* Yc) {
    gemm(4 * N, BB * Fin, N, Pst, N, X, BB * Fin, U, BB * Fin, nullptr, 1.f, 0.f);
    gemm_gather(N * BB, Fout, Fin, U, N * BB * Fin, w, Yc);
}

// decoder order: Z_k = X @ W_k ; Y = PTcat @ Zstack
static void dec_layer(const float* X, int N, int Fin, int Fout, const float* PT,
                      const float* w, float* Z, float* Yc) {
    for (int k = 0; k < 4; k++)
        gemm(N * BB, Fout, Fin, X, Fin, w + k * Fin * Fout, Fout,
             Z + k * N * BB * Fout, Fout, nullptr, 1.f, 0.f);
    gemm(N, BB * Fout, 4 * N, PT, 4 * N, Z, BB * Fout, Yc, BB * Fout, nullptr, 1.f, 0.f);
}

static void bn(const float* src, float* dst, int R, int F,
               const float* g, const float* b, float* ST) {
    zero_k<<<1, 512>>>(ST, 2 * F);
    dim3 blk(F, 256 / F);
    int blocks = imax(1, imin(1024, R / imax(1, (256 / F) * 128)));
    bn_stats_k<<<blocks, blk>>>(src, R, F, ST);
    int tot = R * F;
    bn_apply_k<<<(tot + 255) / 256, 256>>>(src, dst, R, F, ST, g, b);
}

// ---------------- entry point ----------------
extern "C" void kernel_launch(void* const* d_in, const int* in_sizes, int n_in,
                              void* d_out, int out_size) {
    const float* x    = (const float*)d_in[0];
    const float* L3i  = (const float*)d_in[1];
    const float* L2i  = (const float*)d_in[2];
    const float* L1i  = (const float*)d_in[3];
    const float* L0i  = (const float*)d_in[4];
    const float* w_e3a = (const float*)d_in[5];
    const float* ga_e3a = (const float*)d_in[6];
    const float* be_e3a = (const float*)d_in[7];
    const float* w_e3b = (const float*)d_in[8];
    const float* ga_e3b = (const float*)d_in[9];
    const float* be_e3b = (const float*)d_in[10];
    const float* w_e2 = (const float*)d_in[11];
    const float* ga_e2 = (const float*)d_in[12];
    const float* be_e2 = (const float*)d_in[13];
    const float* w_e1 = (const float*)d_in[14];
    const float* ga_e1 = (const float*)d_in[15];
    const float* be_e1 = (const float*)d_in[16];
    const float* w_e0 = (const float*)d_in[17];
    const float* ga_e0 = (const float*)d_in[18];
    const float* be_e0 = (const float*)d_in[19];
    const float* w_d1 = (const float*)d_in[20];
    const float* ga_d1 = (const float*)d_in[21];
    const float* be_d1 = (const float*)d_in[22];
    const float* w_d2 = (const float*)d_in[23];
    const float* ga_d2 = (const float*)d_in[24];
    const float* be_d2 = (const float*)d_in[25];
    const float* w_d3 = (const float*)d_in[26];
    const float* ga_d3 = (const float*)d_in[27];
    const float* be_d3 = (const float*)d_in[28];
    const float* w_out = (const float*)d_in[29];
    float* out = (float*)d_out;

    float *X0 = sym(g_X0), *U = sym(g_U), *Y = sym(g_Y);
    float *S3 = sym(g_S3), *S2 = sym(g_S2), *S1 = sym(g_S1);
    float *Fo = sym(g_F), *ST = sym(g_ST);
    float *P3 = sym(g_P3), *PT3 = sym(g_PT3);
    float *P2 = sym(g_P2), *PT2 = sym(g_PT2);
    float *P1 = sym(g_P1), *PT1 = sym(g_PT1);
    float *P0 = sym(g_P0);

    // Chebyshev polynomial matrices per level
    buildP(L3i, 768, P3, PT3);
    buildP(L2i, 192, P2, PT2);
    buildP(L1i,  48, P1, PT1);
    buildP(L0i,  12, P0, nullptr);

    // input permute: (B,C,HW,N) -> (N, BB, 8)
    permute_in_k<<<(768 * 256 * 8 + 255) / 256, 256>>>(x, X0);

    // ---- encoder ----
    enc_layer(X0, 768, 8, 32, P3, w_e3a, U, Y);
    bn(Y, X0, 768 * BB, 32, ga_e3a, be_e3a, ST);

    enc_layer(X0, 768, 32, 64, P3, w_e3b, U, Y);
    bn(Y, S3, 768 * BB, 64, ga_e3b, be_e3b, ST);
    pool_k<<<(192 * BB * 64 + 255) / 256, 256>>>(S3, X0, 192, 64);

    enc_layer(X0, 192, 64, 128, P2, w_e2, U, Y);
    bn(Y, S2, 192 * BB, 128, ga_e2, be_e2, ST);
    pool_k<<<(48 * BB * 128 + 255) / 256, 256>>>(S2, X0, 48, 128);

    enc_layer(X0, 48, 128, 256, P1, w_e1, U, Y);
    bn(Y, S1, 48 * BB, 256, ga_e1, be_e1, ST);
    pool_k<<<(12 * BB * 256 + 255) / 256, 256>>>(S1, X0, 12, 256);

    enc_layer(X0, 12, 256, 256, P0, w_e0, U, Y);
    bn(Y, Y, 12 * BB, 256, ga_e0, be_e0, ST);

    // ---- decoder ----
    concat_k<<<(48 * BB * 512 + 255) / 256, 256>>>(Y, S1, X0, 48, 256, 256);
    dec_layer(X0, 48, 512, 128, PT1, w_d1, U, Y);
    bn(Y, Y, 48 * BB, 128, ga_d1, be_d1, ST);

    concat_k<<<(192 * BB * 256 + 255) / 256, 256>>>(Y, S2, X0, 192, 128, 128);
    dec_layer(X0, 192, 256, 64, PT2, w_d2, U, Y);
    bn(Y, Y, 192 * BB, 64, ga_d2, be_d2, ST);

    concat_k<<<(768 * BB * 128 + 255) / 256, 256>>>(Y, S3, X0, 768, 64, 64);
    dec_layer(X0, 768, 128, 32, PT3, w_d3, U, Y);
    bn(Y, Y, 768 * BB, 32, ga_d3, be_d3, ST);

    // ---- out layer (decoder order, split-K for skinny final GEMM) ----
    for (int k = 0; k < 4; k++)
        gemm(768 * BB, 1, 32, Y, 32, w_out + k * 32, 1, U + k * 768 * BB, 1,
             nullptr, 1.f, 0.f);
    zero_k<<<(196608 + 255) / 256, 256>>>(Fo, 196608);
    gemm_splitk(768, 256, 3072, PT3, 3072, U, 256, Fo, 256, 8);

    permute_out_k<<<(196608 + 255) / 256, 256>>>(Fo, out);
}

// round 5
// speedup vs baseline: 1.0872x; 1.0872x over previous
#include <cuda_runtime.h>
#include <cuda_bf16.h>

#define BB 256   // B*H*W samples

// ---------------- scratch (__device__ globals; allocation-free) ----------------
__device__ float g_X0[25165824];   // layer input   (max 768*256*128)
__device__ float g_U [25165824];   // U / Z stack   (max 3072*8192)
__device__ float g_Y [12582912];   // conv output   (max 768*256*64)
__device__ float g_S3[12582912];   // skip s3 (768,256,64)
__device__ float g_S2[ 6291456];   // skip s2 (192,256,128)
__device__ float g_S1[ 3145728];   // skip s1 (48,256,256)
__device__ float g_F [  196608];   // final (768,256)
__device__ float g_P3[2359296], g_PT3[2359296];
__device__ float g_P2[ 147456], g_PT2[ 147456];
__device__ float g_P1[   9216], g_PT1[   9216];
__device__ float g_P0[    576];
__device__ float g_ST[    512];    // BN sums: [0..F) sum, [F..2F) sumsq

__host__ __device__ __forceinline__ int imin(int a,int b){return a<b?a:b;}
__host__ __device__ __forceinline__ int imax(int a,int b){return a>b?a:b;}

// ================= tensor-core split-bf16 GEMM =================
// C = alpha*A@B + beta*D, fp32 in/out, internally Ah*Bh + Ah*Bl + Al*Bh
// AMODE 0: A[r*lda + k]
// AMODE 1: A[(k>>lgfin)*strideK + r*fin + (k & fin-1)]   (encoder k-gather)
// SPLITK : gridDim.z K-slices (multiples of 16), atomicAdd into pre-zeroed C
__device__ __forceinline__ void mma_bf16(float* c, const unsigned* a, const unsigned* b) {
    asm volatile(
      "mma.sync.aligned.m16n8k16.row.col.f32.bf16.bf16.f32 "
      "{%0,%1,%2,%3},{%4,%5,%6,%7},{%8,%9},{%0,%1,%2,%3};"
      : "+f"(c[0]), "+f"(c[1]), "+f"(c[2]), "+f"(c[3])
      : "r"(a[0]), "r"(a[1]), "r"(a[2]), "r"(a[3]), "r"(b[0]), "r"(b[1]));
}

__device__ __forceinline__ void split_store(float x, __nv_bfloat16* ph, __nv_bfloat16* pl) {
    __nv_bfloat16 h = __float2bfloat16(x);
    *ph = h;
    *pl = __float2bfloat16(x - __bfloat162float(h));
}

template<int AMODE, bool SPLITK>
__global__ void __launch_bounds__(256)
gemm_tc(int M, int Nc, int K,
        const float* __restrict__ A, int lda,
        const float* __restrict__ B, int ldb,
        float* __restrict__ C, int ldc,
        const float* __restrict__ D, float alpha, float beta,
        int fin, int lgfin, int strideK)
{
    // smem planes, row pitch 24 bf16 (48B) -> conflict-free 4B fragment loads
    __shared__ __nv_bfloat16 sAh[128*24], sAl[128*24];
    __shared__ __nv_bfloat16 sBh[ 64*24], sBl[ 64*24];

    const int row0 = blockIdx.y << 7;
    const int col0 = blockIdx.x << 6;
    const int tid  = threadIdx.x;
    const int warp = tid >> 5, lane = tid & 31;
    const int m_w  = (warp >> 1) << 5;   // warp grid 4x2 -> 32x32 warp tile
    const int n_w  = (warp &  1) << 5;
    const int g    = lane >> 2, tg = lane & 3;

    int kb = 0, ke = K;
    if (SPLITK) {
        int ks = (((K + (int)gridDim.z - 1) / (int)gridDim.z) + 15) & ~15;
        kb = blockIdx.z * ks;
        ke = imin(K, kb + ks);
        if (kb >= ke) return;
    }

    float acc[2][4][4] = {};

    const int am = tid >> 1, ak0 = (tid & 1) << 3;   // A staging: row am, k ak0..+7
    const int bn = tid >> 2, bk0 = (tid & 3) << 2;   // B staging: col bn, k bk0..+3

    for (int kt = kb; kt < ke; kt += 16) {
        { // stage A (128x16)
            int gr = row0 + am;
            #pragma unroll
            for (int j = 0; j < 8; j++) {
                int kk = ak0 + j, gk = kt + kk;
                float x = 0.f;
                if (gr < M && gk < ke) {
                    int addr;
                    if (AMODE == 0) addr = gr * lda + gk;
                    else            addr = (gk >> lgfin) * strideK + gr * fin + (gk & (fin - 1));
                    x = A[addr];
                }
                split_store(x, &sAh[am * 24 + kk], &sAl[am * 24 + kk]);
            }
        }
        { // stage B (16x64), stored transposed [n][k]
            int gc = col0 + bn;
            #pragma unroll
            for (int j = 0; j < 4; j++) {
                int kk = bk0 + j, gk = kt + kk;
                float x = (gc < Nc && gk < ke) ? B[gk * ldb + gc] : 0.f;
                split_store(x, &sBh[bn * 24 + kk], &sBl[bn * 24 + kk]);
            }
        }
        __syncthreads();

        unsigned ah[2][4], al[2][4], bh[4][2], bl[4][2];
        #pragma unroll
        for (int mi = 0; mi < 2; mi++) {
            int r0 = (m_w + mi * 16 + g) * 24 + 2 * tg;
            int r1 = r0 + 8 * 24;
            ah[mi][0] = *(const unsigned*)&sAh[r0];
            ah[mi][1] = *(const unsigned*)&sAh[r1];
            ah[mi][2] = *(const unsigned*)&sAh[r0 + 8];
            ah[mi][3] = *(const unsigned*)&sAh[r1 + 8];
            al[mi][0] = *(const unsigned*)&sAl[r0];
            al[mi][1] = *(const unsigned*)&sAl[r1];
            al[mi][2] = *(const unsigned*)&sAl[r0 + 8];
            al[mi][3] = *(const unsigned*)&sAl[r1 + 8];
        }
        #pragma unroll
        for (int ni = 0; ni < 4; ni++) {
            int c0 = (n_w + ni * 8 + g) * 24 + 2 * tg;
            bh[ni][0] = *(const unsigned*)&sBh[c0];
            bh[ni][1] = *(const unsigned*)&sBh[c0 + 8];
            bl[ni][0] = *(const unsigned*)&sBl[c0];
            bl[ni][1] = *(const unsigned*)&sBl[c0 + 8];
        }
        #pragma unroll
        for (int mi = 0; mi < 2; mi++)
            #pragma unroll
            for (int ni = 0; ni < 4; ni++) {
                mma_bf16(acc[mi][ni], ah[mi], bh[ni]);
                mma_bf16(acc[mi][ni], ah[mi], bl[ni]);
                mma_bf16(acc[mi][ni], al[mi], bh[ni]);
            }
        __syncthreads();
    }

    // epilogue
    #pragma unroll
    for (int mi = 0; mi < 2; mi++)
        #pragma unroll
        for (int ni = 0; ni < 4; ni++) {
            int gr = row0 + m_w + mi * 16 + g;
            int gc = col0 + n_w + ni * 8 + 2 * tg;
            if (gc >= Nc) continue;           // Nc always even, gc even -> gc+1 valid
            const float* cp = acc[mi][ni];
            #pragma unroll
            for (int h = 0; h < 2; h++) {
                int r = gr + h * 8;
                if (r >= M) continue;
                int o = r * ldc + gc;
                float v0 = cp[2 * h], v1 = cp[2 * h + 1];
                if (SPLITK) {
                    atomicAdd(&C[o], v0);
                    atomicAdd(&C[o + 1], v1);
                } else {
                    v0 *= alpha; v1 *= alpha;
                    if (D != nullptr) { v0 += beta * D[o]; v1 += beta * D[o + 1]; }
                    *(float2*)&C[o] = make_float2(v0, v1);
                }
            }
        }
}

// ---------------- fp32 fallback SGEMM (tiny shapes only) ----------------
template<int AMODE, bool SPLITK>
__global__ void __launch_bounds__(256)
gemm_k(int M, int Nc, int K,
       const float* __restrict__ A, int lda,
       const float* __restrict__ B, int ldb,
       float* __restrict__ C, int ldc,
       const float* __restrict__ D, float alpha, float beta,
       int fin, int strideK)
{
    __shared__ float As[16][65];
    __shared__ float Bs[16][65];
    const int row0 = blockIdx.y << 6;
    const int col0 = blockIdx.x << 6;
    const int tid  = threadIdx.y * 16 + threadIdx.x;

    int kb = 0, ke = K;
    if (SPLITK) {
        int ks = (K + gridDim.z - 1) / gridDim.z;
        kb = blockIdx.z * ks;
        ke = imin(K, kb + ks);
        if (kb >= ke) return;
    }

    float acc[4][4] = {};

    for (int kt = kb; kt < ke; kt += 16) {
        #pragma unroll
        for (int l = 0; l < 4; l++) {
            int e = tid + (l << 8);
            int m = e >> 4, kk = e & 15;
            int gr = row0 + m, gk = kt + kk;
            float v = 0.f;
            if (gr < M && gk < ke) {
                int addr;
                if (AMODE == 0) addr = gr * lda + gk;
                else            addr = (gk / fin) * strideK + gr * fin + (gk % fin);
                v = A[addr];
            }
            As[kk][m] = v;
        }
        #pragma unroll
        for (int l = 0; l < 4; l++) {
            int e = tid + (l << 8);
            int kk = e >> 6, n = e & 63;
            int gk = kt + kk, gc = col0 + n;
            float v = 0.f;
            if (gk < ke && gc < Nc) v = B[gk * ldb + gc];
            Bs[kk][n] = v;
        }
        __syncthreads();
        #pragma unroll
        for (int kk = 0; kk < 16; kk++) {
            float ra[4], rb[4];
            #pragma unroll
            for (int i = 0; i < 4; i++) ra[i] = As[kk][(threadIdx.y << 2) + i];
            #pragma unroll
            for (int j = 0; j < 4; j++) rb[j] = Bs[kk][(threadIdx.x << 2) + j];
            #pragma unroll
            for (int i = 0; i < 4; i++)
                #pragma unroll
                for (int j = 0; j < 4; j++)
                    acc[i][j] += ra[i] * rb[j];
        }
        __syncthreads();
    }

    #pragma unroll
    for (int i = 0; i < 4; i++) {
        int gr = row0 + (threadIdx.y << 2) + i;
        if (gr >= M) continue;
        #pragma unroll
        for (int j = 0; j < 4; j++) {
            int gc = col0 + (threadIdx.x << 2) + j;
            if (gc >= Nc) continue;
            float v = alpha * acc[i][j];
            int addr = gr * ldc + gc;
            if (SPLITK) atomicAdd(&C[addr], v);
            else {
                if (D != nullptr) v += beta * D[addr];
                C[addr] = v;
            }
        }
    }
}

// ---------------- small kernels ----------------
__global__ void zero_k(float* p, int n) {
    int i = blockIdx.x * blockDim.x + threadIdx.x;
    if (i < n) p[i] = 0.f;
}

__global__ void initP_k(float* __restrict__ P, const float* __restrict__ L, int N, int NN) {
    int i = blockIdx.x * blockDim.x + threadIdx.x;
    if (i >= 2 * NN) return;
    if (i < NN) P[i] = ((i / N) == (i % N)) ? 1.f : 0.f;
    else        P[i] = L[i - NN];
}

// PT[n][k*N+m] = P[k][n][m]
__global__ void transP_k(const float* __restrict__ P, float* __restrict__ PT, int N, int NN) {
    int i = blockIdx.x * blockDim.x + threadIdx.x;
    if (i >= 4 * NN) return;
    int k = i / NN, r = i - k * NN;
    int n = r / N,  m = r - n * N;
    PT[(n * 4 + k) * N + m] = P[i];
}

// x (4,8,8*8,768) -> X0 (768, 256, 8)
__global__ void permute_in_k(const float* __restrict__ x, float* __restrict__ dst) {
    int i = blockIdx.x * blockDim.x + threadIdx.x;
    if (i >= 768 * 256 * 8) return;
    int n = i >> 11;
    int rem = i & 2047;
    int bb = rem >> 3;
    int c  = rem & 7;
    int b  = bb >> 6, hw = bb & 63;
    dst[i] = x[(((b * 8 + c) * 64) + hw) * 768 + n];
}

// F (768,256) -> out (256,768)
__global__ void permute_out_k(const float* __restrict__ Fm, float* __restrict__ out) {
    int i = blockIdx.x * blockDim.x + threadIdx.x;
    if (i >= 196608) return;
    int bb = i / 768, n = i - bb * 768;
    out[i] = Fm[n * 256 + bb];
}

// healpix 4:1 max pool on (N, BB, F) node axis
__global__ void pool_k(const float* __restrict__ src, float* __restrict__ dst, int Np, int F) {
    int i = blockIdx.x * blockDim.x + threadIdx.x;
    int rowsz = BB * F;
    int tot = Np * rowsz;
    if (i >= tot) return;
    int n4 = i / rowsz, rem = i - n4 * rowsz;
    const float* s = src + (4 * n4) * rowsz + rem;
    float v = s[0];
    v = fmaxf(v, s[rowsz]);
    v = fmaxf(v, s[2 * rowsz]);
    v = fmaxf(v, s[3 * rowsz]);
    dst[i] = v;
}

// dst (N,BB,Fa+Fb) = concat(unpool(H (N/4,BB,Fa)), S (N,BB,Fb))
__global__ void concat_k(const float* __restrict__ H, const float* __restrict__ S,
                         float* __restrict__ dst, int N, int Fa, int Fb) {
    int Ft = Fa + Fb;
    int i = blockIdx.x * blockDim.x + threadIdx.x;
    int tot = N * BB * Ft;
    if (i >= tot) return;
    int n = i / (BB * Ft);
    int rem = i - n * (BB * Ft);
    int bb = rem / Ft;
    int f  = rem - bb * Ft;
    float v;
    if (f < Fa) v = H[((n >> 2) * BB + bb) * Fa + f];
    else        v = S[(n * BB + bb) * Fb + (f - Fa)];
    dst[i] = v;
}

// BN stats
__global__ void bn_stats_k(const float* __restrict__ Y, int R, int F, float* __restrict__ ST) {
    __shared__ float ssum[256];
    __shared__ float ssq [256];
    int tx = threadIdx.x, ty = threadIdx.y;
    int tid = ty * F + tx;
    int rpb = (R + gridDim.x - 1) / gridDim.x;
    int r0 = blockIdx.x * rpb;
    int r1 = imin(R, r0 + rpb);
    float s = 0.f, q = 0.f;
    for (int r = r0 + ty; r < r1; r += blockDim.y) {
        float v = Y[r * F + tx];
        s += v; q += v * v;
    }
    ssum[tid] = s; ssq[tid] = q;
    __syncthreads();
    if (ty == 0) {
        for (int yy = 1; yy < blockDim.y; yy++) {
            s += ssum[yy * F + tx];
            q += ssq [yy * F + tx];
        }
        atomicAdd(&ST[tx], s);
        atomicAdd(&ST[F + tx], q);
    }
}

__global__ void bn_apply_k(const float* __restrict__ src, float* __restrict__ dst,
                           int R, int F, const float* __restrict__ ST,
                           const float* __restrict__ g, const float* __restrict__ b) {
    int i = blockIdx.x * blockDim.x + threadIdx.x;
    int tot = R * F;
    if (i >= tot) return;
    int f = i % F;
    float m = (float)R;
    float mu = ST[f] / m;
    float var = ST[F + f] / m - mu * mu;
    float v = (src[i] - mu) * rsqrtf(var + 1e-5f) * g[f] + b[f];
    dst[i] = v > 0.f ? v : 0.f;
}

// ---------------- host helpers ----------------
template<typename T> static float* sym(T& s) {
    void* p = nullptr;
    cudaGetSymbolAddress(&p, s);
    return (float*)p;
}

static int ilog2(int v) { int l = 0; while ((1 << l) < v) l++; return l; }

static void gemm_f32(int M, int Nc, int K, const float* A, int lda, const float* B, int ldb,
                     float* C, int ldc, const float* D, float alpha, float beta) {
    dim3 g((Nc + 63) / 64, (M + 63) / 64, 1), b(16, 16);
    gemm_k<0, false><<<g, b>>>(M, Nc, K, A, lda, B, ldb, C, ldc, D, alpha, beta, 0, 0);
}

static void gemm_tc0(int M, int Nc, int K, const float* A, int lda, const float* B, int ldb,
                     float* C, int ldc, const float* D, float alpha, float beta) {
    dim3 g((Nc + 63) / 64, (M + 127) / 128, 1);
    gemm_tc<0, false><<<g, 256>>>(M, Nc, K, A, lda, B, ldb, C, ldc, D, alpha, beta, 0, 0, 0);
}

static void gemm_tc_gather(int M, int Nc, int Fin, const float* U, int strideK,
                           const float* B, float* C) {
    int K = 4 * Fin;
    dim3 g((Nc + 63) / 64, (M + 127) / 128, 1);
    gemm_tc<1, false><<<g, 256>>>(M, Nc, K, U, 0, B, Nc, C, Nc, nullptr, 1.f, 0.f,
                                  Fin, ilog2(Fin), strideK);
}

static void gemm_tc_splitk(int M, int Nc, int K, const float* A, int lda, const float* B, int ldb,
                           float* C, int ldc, int slices) {
    dim3 g((Nc + 63) / 64, (M + 127) / 128, slices);
    gemm_tc<0, true><<<g, 256>>>(M, Nc, K, A, lda, B, ldb, C, ldc, nullptr, 1.f, 0.f, 0, 0, 0);
}

static void buildP(const float* L, int N, float* P, float* PT) {
    int NN = N * N;
    initP_k<<<(2 * NN + 255) / 256, 256>>>(P, L, N, NN);
    if (N >= 192) {
        gemm_tc0(N, N, N, L, N, P + NN,     N, P + 2 * NN, N, P,      2.f, -1.f);
        gemm_tc0(N, N, N, L, N, P + 2 * NN, N, P + 3 * NN, N, P + NN, 2.f, -1.f);
    } else {
        gemm_f32(N, N, N, L, N, P + NN,     N, P + 2 * NN, N, P,      2.f, -1.f);
        gemm_f32(N, N, N, L, N, P + 2 * NN, N, P + 3 * NN, N, P + NN, 2.f, -1.f);
    }
    if (PT) transP_k<<<(4 * NN + 255) / 256, 256>>>(P, PT, N, NN);
}

// encoder order: U = Pstack @ X ; Y = gather_k(U) @ w
static void enc_layer(const float* X, int N, int Fin, int Fout, const float* Pst,
                      const float* w, float* U, float* Yc) {
    gemm_tc0(4 * N, BB * Fin, N, Pst, N, X, BB * Fin, U, BB * Fin, nullptr, 1.f, 0.f);
    gemm_tc_gather(N * BB, Fout, Fin, U, N * BB * Fin, w, Yc);
}

// decoder order: Z_k = X @ W_k ; Y = PTcat @ Zstack
static void dec_layer(const float* X, int N, int Fin, int Fout, const float* PT,
                      const float* w, float* Z, float* Yc) {
    for (int k = 0; k < 4; k++)
        gemm_tc0(N * BB, Fout, Fin, X, Fin, w + k * Fin * Fout, Fout,
                 Z + k * N * BB * Fout, Fout, nullptr, 1.f, 0.f);
    gemm_tc0(N, BB * Fout, 4 * N, PT, 4 * N, Z, BB * Fout, Yc, BB * Fout, nullptr, 1.f, 0.f);
}

static void bn(const float* src, float* dst, int R, int F,
               const float* g, const float* b, float* ST) {
    zero_k<<<1, 512>>>(ST, 2 * F);
    dim3 blk(F, 256 / F);
    int blocks = imax(1, imin(1024, R / imax(1, (256 / F) * 128)));
    bn_stats_k<<<blocks, blk>>>(src, R, F, ST);
    int tot = R * F;
    bn_apply_k<<<(tot + 255) / 256, 256>>>(src, dst, R, F, ST, g, b);
}

// ---------------- entry point ----------------
extern "C" void kernel_launch(void* const* d_in, const int* in_sizes, int n_in,
                              void* d_out, int out_size) {
    const float* x    = (const float*)d_in[0];
    const float* L3i  = (const float*)d_in[1];
    const float* L2i  = (const float*)d_in[2];
    const float* L1i  = (const float*)d_in[3];
    const float* L0i  = (const float*)d_in[4];
    const float* w_e3a = (const float*)d_in[5];
    const float* ga_e3a = (const float*)d_in[6];
    const float* be_e3a = (const float*)d_in[7];
    const float* w_e3b = (const float*)d_in[8];
    const float* ga_e3b = (const float*)d_in[9];
    const float* be_e3b = (const float*)d_in[10];
    const float* w_e2 = (const float*)d_in[11];
    const float* ga_e2 = (const float*)d_in[12];
    const float* be_e2 = (const float*)d_in[13];
    const float* w_e1 = (const float*)d_in[14];
    const float* ga_e1 = (const float*)d_in[15];
    const float* be_e1 = (const float*)d_in[16];
    const float* w_e0 = (const float*)d_in[17];
    const float* ga_e0 = (const float*)d_in[18];
    const float* be_e0 = (const float*)d_in[19];
    const float* w_d1 = (const float*)d_in[20];
    const float* ga_d1 = (const float*)d_in[21];
    const float* be_d1 = (const float*)d_in[22];
    const float* w_d2 = (const float*)d_in[23];
    const float* ga_d2 = (const float*)d_in[24];
    const float* be_d2 = (const float*)d_in[25];
    const float* w_d3 = (const float*)d_in[26];
    const float* ga_d3 = (const float*)d_in[27];
    const float* be_d3 = (const float*)d_in[28];
    const float* w_out = (const float*)d_in[29];
    float* out = (float*)d_out;

    float *X0 = sym(g_X0), *U = sym(g_U), *Y = sym(g_Y);
    float *S3 = sym(g_S3), *S2 = sym(g_S2), *S1 = sym(g_S1);
    float *Fo = sym(g_F), *ST = sym(g_ST);
    float *P3 = sym(g_P3), *PT3 = sym(g_PT3);
    float *P2 = sym(g_P2), *PT2 = sym(g_PT2);
    float *P1 = sym(g_P1), *PT1 = sym(g_PT1);
    float *P0 = sym(g_P0);

    // Chebyshev polynomial matrices per level
    buildP(L3i, 768, P3, PT3);
    buildP(L2i, 192, P2, PT2);
    buildP(L1i,  48, P1, PT1);
    buildP(L0i,  12, P0, nullptr);

    // input permute: (B,C,HW,N) -> (N, BB, 8)
    permute_in_k<<<(768 * 256 * 8 + 255) / 256, 256>>>(x, X0);

    // ---- encoder ----
    enc_layer(X0, 768, 8, 32, P3, w_e3a, U, Y);
    bn(Y, X0, 768 * BB, 32, ga_e3a, be_e3a, ST);

    enc_layer(X0, 768, 32, 64, P3, w_e3b, U, Y);
    bn(Y, S3, 768 * BB, 64, ga_e3b, be_e3b, ST);
    pool_k<<<(192 * BB * 64 + 255) / 256, 256>>>(S3, X0, 192, 64);

    enc_layer(X0, 192, 64, 128, P2, w_e2, U, Y);
    bn(Y, S2, 192 * BB, 128, ga_e2, be_e2, ST);
    pool_k<<<(48 * BB * 128 + 255) / 256, 256>>>(S2, X0, 48, 128);

    enc_layer(X0, 48, 128, 256, P1, w_e1, U, Y);
    bn(Y, S1, 48 * BB, 256, ga_e1, be_e1, ST);
    pool_k<<<(12 * BB * 256 + 255) / 256, 256>>>(S1, X0, 12, 256);

    enc_layer(X0, 12, 256, 256, P0, w_e0, U, Y);
    bn(Y, Y, 12 * BB, 256, ga_e0, be_e0, ST);

    // ---- decoder ----
    concat_k<<<(48 * BB * 512 + 255) / 256, 256>>>(Y, S1, X0, 48, 256, 256);
    dec_layer(X0, 48, 512, 128, PT1, w_d1, U, Y);
    bn(Y, Y, 48 * BB, 128, ga_d1, be_d1, ST);

    concat_k<<<(192 * BB * 256 + 255) / 256, 256>>>(Y, S2, X0, 192, 128, 128);
    dec_layer(X0, 192, 256, 64, PT2, w_d2, U, Y);
    bn(Y, Y, 192 * BB, 64, ga_d2, be_d2, ST);

    concat_k<<<(768 * BB * 128 + 255) / 256, 256>>>(Y, S3, X0, 768, 64, 64);
    dec_layer(X0, 768, 128, 32, PT3, w_d3, U, Y);
    bn(Y, Y, 768 * BB, 32, ga_d3, be_d3, ST);

    // ---- out layer ----
    for (int k = 0; k < 4; k++)
        gemm_f32(768 * BB, 1, 32, Y, 32, w_out + k * 32, 1, U + k * 768 * BB, 1,
                 nullptr, 1.f, 0.f);
    zero_k<<<(196608 + 255) / 256, 256>>>(Fo, 196608);
    gemm_tc_splitk(768, 256, 3072, PT3, 3072, U, 256, Fo, 256, 8);

    permute_out_k<<<(196608 + 255) / 256, 256>>>(Fo, out);
}

// round 13
// speedup vs baseline: 1.5772x; 1.4507x over previous
#include <cuda_runtime.h>
#include <cuda_bf16.h>

#define BB 256
typedef __nv_bfloat16 bf16;

// ---------------- scratch (__device__ globals; allocation-free) ----------------
__device__ __align__(16) bf16 g_Xh[25165824], g_Xl[25165824];   // layer input dual
__device__ __align__(16) bf16 g_Uh[25165824], g_Ul[25165824];   // U / Z-stack dual
__device__ __align__(16) bf16 g_Yh[12582912], g_Yl[12582912];   // conv output dual
__device__ __align__(16) bf16 g_S3h[12582912], g_S3l[12582912];
__device__ __align__(16) bf16 g_S2h[ 6291456], g_S2l[ 6291456];
__device__ __align__(16) bf16 g_S1h[ 3145728], g_S1l[ 3145728];
__device__ __align__(16) bf16 g_Wh[262144], g_Wl[262144];
__device__ __align__(16) bf16 g_P3dh[2359296], g_P3dl[2359296];
__device__ __align__(16) bf16 g_PT3dh[2359296], g_PT3dl[2359296];
__device__ __align__(16) bf16 g_P2dh[ 147456], g_P2dl[ 147456];
__device__ __align__(16) bf16 g_PT2dh[ 147456], g_PT2dl[ 147456];
__device__ __align__(16) bf16 g_P1dh[   9216], g_P1dl[   9216];
__device__ __align__(16) bf16 g_PT1dh[   9216], g_PT1dl[   9216];
__device__ __align__(16) bf16 g_P0dh[    576], g_P0dl[    576];
__device__ __align__(16) float g_P3[2359296], g_P2[147456], g_P1[9216], g_P0[576];
__device__ __align__(16) float g_F[196608];
__device__ __align__(16) float g_ST[512];

__host__ __device__ __forceinline__ int imin(int a,int b){return a<b?a:b;}
__host__ __device__ __forceinline__ int imax(int a,int b){return a>b?a:b;}

__device__ __forceinline__ void fsplit(float x, bf16& h, bf16& l) {
    h = __float2bfloat16(x);
    l = __float2bfloat16(x - __bfloat162float(h));
}
__device__ __forceinline__ float dread(const bf16* __restrict__ H,
                                       const bf16* __restrict__ L, int i) {
    return __bfloat162float(H[i]) + __bfloat162float(L[i]);
}

__device__ __forceinline__ void mma_bf16(float* c, const unsigned* a, const unsigned* b) {
    asm volatile(
      "mma.sync.aligned.m16n8k16.row.col.f32.bf16.bf16.f32 "
      "{%0,%1,%2,%3},{%4,%5,%6,%7},{%8,%9},{%0,%1,%2,%3};"
      : "+f"(c[0]), "+f"(c[1]), "+f"(c[2]), "+f"(c[3])
      : "r"(a[0]), "r"(a[1]), "r"(a[2]), "r"(a[3]), "r"(b[0]), "r"(b[1]));
}

// ================= dual-bf16 tensor-core GEMM =================
// Logical: C = A@B with near-fp32 precision via AhBh + AhBl + AlBh
// AMODE 0: A[r*lda + k] ; AMODE 1: A[(k>>lgfin)*strideK + r*fin + (k&(fin-1))]
// EMODE 1: dual bf16 out (Ch/Cl) ; EMODE 2: split-K fp32 atomicAdd into Cf
// SCATTER (with EMODE1): col c -> addr (c>>lgF)*scPlane + r*Fsc + (c&(Fsc-1))
#define PITCH 40   // bf16 per smem row (32 data + 8 pad) -> conflict-free frags

template<int AMODE, int EMODE, bool SCATTER>
__global__ void __launch_bounds__(256, 2)
gemm_tc2(int M, int Nc, int K,
         const bf16* __restrict__ Ah, const bf16* __restrict__ Al, int lda,
         const bf16* __restrict__ Bh, const bf16* __restrict__ Bl, int ldb,
         bf16* __restrict__ Ch, bf16* __restrict__ Cl,
         float* __restrict__ Cf, int ldc,
         int fin, int lgfin, int strideK, int lgF, int scPlane)
{
    __shared__ __align__(16) bf16 sAh[128 * PITCH], sAl[128 * PITCH];
    __shared__ __align__(16) bf16 sBh[ 64 * PITCH], sBl[ 64 * PITCH];

    const int row0 = blockIdx.y << 7;
    const int col0 = blockIdx.x << 6;
    const int tid  = threadIdx.x;
    const int warp = tid >> 5, lane = tid & 31;
    const int m_w  = (warp >> 1) << 5;
    const int n_w  = (warp &  1) << 5;
    const int g    = lane >> 2, tg = lane & 3;

    int kb = 0, ke = K;
    if (EMODE == 2) {
        int ks = (((K + (int)gridDim.z - 1) / (int)gridDim.z) + 31) & ~31;
        kb = blockIdx.z * ks;
        ke = imin(K, kb + ks);
        if (kb >= ke) return;
    }

    float acc[2][4][4] = {};

    const int arow = tid >> 1, ahalf = tid & 1;        // A: 128 rows x 32 k
    const int bk   = tid >> 3, bn0   = (tid & 7) << 3; // B: 32 k x 64 n
    // vector-path legality: 16B loads need 8-element-aligned addresses
    const bool avec = (AMODE == 1) || ((lda & 7) == 0);
    const bool bvec = ((ldb & 7) == 0);

    for (int kt = kb; kt < ke; kt += 32) {
        // ---- stage A (both planes) ----
        #pragma unroll
        for (int p = 0; p < 2; p++) {
            const bf16* As = p ? Al : Ah;
            bf16* Ad = p ? sAl : sAh;
            int gr = row0 + arow;
            #pragma unroll
            for (int c = 0; c < 2; c++) {
                int k8 = kt + ahalf * 16 + c * 8;
                int so = arow * PITCH + ahalf * 16 + c * 8;
                if (avec && gr < M && k8 + 8 <= ke) {
                    int addr = (AMODE == 0) ? gr * lda + k8
                             : (k8 >> lgfin) * strideK + gr * fin + (k8 & (fin - 1));
                    *(uint4*)&Ad[so] = *(const uint4*)&As[addr];
                } else {
                    #pragma unroll
                    for (int j = 0; j < 8; j++) {
                        int k = k8 + j;
                        bf16 v = __float2bfloat16(0.f);
                        if (gr < M && k < ke) {
                            int addr = (AMODE == 0) ? gr * lda + k
                                     : (k >> lgfin) * strideK + gr * fin + (k & (fin - 1));
                            v = As[addr];
                        }
                        Ad[so + j] = v;
                    }
                }
            }
        }
        // ---- stage B (both planes), transpose to [n][k] ----
        #pragma unroll
        for (int p = 0; p < 2; p++) {
            const bf16* Bs = p ? Bl : Bh;
            bf16* Bd = p ? sBl : sBh;
            int gk = kt + bk;
            bf16 vals[8];
            if (gk < ke && bvec && col0 + bn0 + 8 <= Nc) {
                uint4 v = *(const uint4*)&Bs[gk * ldb + col0 + bn0];
                *(uint4*)vals = v;
            } else {
                #pragma unroll
                for (int j = 0; j < 8; j++) {
                    int gc = col0 + bn0 + j;
                    vals[j] = (gk < ke && gc < Nc) ? Bs[gk * ldb + gc]
                                                   : __float2bfloat16(0.f);
                }
            }
            #pragma unroll
            for (int j = 0; j < 8; j++)
                Bd[(bn0 + j) * PITCH + bk] = vals[j];
        }
        __syncthreads();

        // ---- two 16-k MMA steps ----
        #pragma unroll
        for (int s = 0; s < 2; s++) {
            unsigned ah[2][4], al[2][4], bh[4][2], bl[4][2];
            #pragma unroll
            for (int mi = 0; mi < 2; mi++) {
                int base = (m_w + mi * 16 + g) * PITCH + s * 16 + 2 * tg;
                ah[mi][0] = *(const unsigned*)&sAh[base];
                ah[mi][1] = *(const unsigned*)&sAh[base + 8 * PITCH];
                ah[mi][2] = *(const unsigned*)&sAh[base + 8];
                ah[mi][3] = *(const unsigned*)&sAh[base + 8 * PITCH + 8];
                al[mi][0] = *(const unsigned*)&sAl[base];
                al[mi][1] = *(const unsigned*)&sAl[base + 8 * PITCH];
                al[mi][2] = *(const unsigned*)&sAl[base + 8];
                al[mi][3] = *(const unsigned*)&sAl[base + 8 * PITCH + 8];
            }
            #pragma unroll
            for (int ni = 0; ni < 4; ni++) {
                int base = (n_w + ni * 8 + g) * PITCH + s * 16 + 2 * tg;
                bh[ni][0] = *(const unsigned*)&sBh[base];
                bh[ni][1] = *(const unsigned*)&sBh[base + 8];
                bl[ni][0] = *(const unsigned*)&sBl[base];
                bl[ni][1] = *(const unsigned*)&sBl[base + 8];
            }
            #pragma unroll
            for (int mi = 0; mi < 2; mi++)
                #pragma unroll
                for (int ni = 0; ni < 4; ni++) {
                    mma_bf16(acc[mi][ni], ah[mi], bh[ni]);
                    mma_bf16(acc[mi][ni], ah[mi], bl[ni]);
                    mma_bf16(acc[mi][ni], al[mi], bh[ni]);
                }
        }
        __syncthreads();
    }

    // ---- epilogue ----
    const int Fsc = 1 << lgF;
    #pragma unroll
    for (int mi = 0; mi < 2; mi++)
        #pragma unroll
        for (int ni = 0; ni < 4; ni++) {
            int gc = col0 + n_w + ni * 8 + 2 * tg;
            const float* cp = acc[mi][ni];
            #pragma unroll
            for (int h = 0; h < 2; h++) {
                int r = row0 + m_w + mi * 16 + g + h * 8;
                if (r >= M) continue;
                float v0 = cp[2 * h], v1 = cp[2 * h + 1];
                if (EMODE == 2) {
                    if (gc < Nc)     atomicAdd(&Cf[r * ldc + gc], v0);
                    if (gc + 1 < Nc) atomicAdd(&Cf[r * ldc + gc + 1], v1);
                } else if (SCATTER) {
                    if (gc < Nc) {
                        int a = (gc >> lgF) * scPlane + r * Fsc + (gc & (Fsc - 1));
                        fsplit(v0, Ch[a], Cl[a]);
                    }
                    if (gc + 1 < Nc) {
                        int c1 = gc + 1;
                        int a = (c1 >> lgF) * scPlane + r * Fsc + (c1 & (Fsc - 1));
                        fsplit(v1, Ch[a], Cl[a]);
                    }
                } else {
                    if (gc >= Nc) continue;   // Nc even in all dual uses
                    __nv_bfloat162 th, tl;
                    fsplit(v0, th.x, tl.x);
                    fsplit(v1, th.y, tl.y);
                    int o = r * ldc + gc;
                    *(__nv_bfloat162*)&Ch[o] = th;
                    *(__nv_bfloat162*)&Cl[o] = tl;
                }
            }
        }
}

// ---------------- fp32 SIMT GEMM (buildP only): C = alpha*A@B + beta*D ----------------
__global__ void __launch_bounds__(256)
gemm_f32k(int M, int Nc, int K,
          const float* __restrict__ A, int lda,
          const float* __restrict__ B, int ldb,
          float* __restrict__ C, int ldc,
          const float* __restrict__ D, float alpha, float beta)
{
    __shared__ float As[16][65];
    __shared__ float Bs[16][65];
    const int row0 = blockIdx.y << 6;
    const int col0 = blockIdx.x << 6;
    const int tid  = threadIdx.y * 16 + threadIdx.x;
    float acc[4][4] = {};
    for (int kt = 0; kt < K; kt += 16) {
        #pragma unroll
        for (int l = 0; l < 4; l++) {
            int e = tid + (l << 8);
            int m = e >> 4, kk = e & 15;
            int gr = row0 + m, gk = kt + kk;
            As[kk][m] = (gr < M && gk < K) ? A[gr * lda + gk] : 0.f;
        }
        #pragma unroll
        for (int l = 0; l < 4; l++) {
            int e = tid + (l << 8);
            int kk = e >> 6, n = e & 63;
            int gk = kt + kk, gc = col0 + n;
            Bs[kk][n] = (gk < K && gc < Nc) ? B[gk * ldb + gc] : 0.f;
        }
        __syncthreads();
        #pragma unroll
        for (int kk = 0; kk < 16; kk++) {
            float ra[4], rb[4];
            #pragma unroll
            for (int i = 0; i < 4; i++) ra[i] = As[kk][(threadIdx.y << 2) + i];
            #pragma unroll
            for (int j = 0; j < 4; j++) rb[j] = Bs[kk][(threadIdx.x << 2) + j];
            #pragma unroll
            for (int i = 0; i < 4; i++)
                #pragma unroll
                for (int j = 0; j < 4; j++)
                    acc[i][j] += ra[i] * rb[j];
        }
        __syncthreads();
    }
    #pragma unroll
    for (int i = 0; i < 4; i++) {
        int gr = row0 + (threadIdx.y << 2) + i;
        if (gr >= M) continue;
        #pragma unroll
        for (int j = 0; j < 4; j++) {
            int gc = col0 + (threadIdx.x << 2) + j;
            if (gc >= Nc) continue;
            float v = alpha * acc[i][j];
            if (D != nullptr) v += beta * D[gr * ldc + gc];
            C[gr * ldc + gc] = v;
        }
    }
}

// ---------------- small kernels ----------------
__global__ void zero_k(float* p, int n) {
    int i = blockIdx.x * blockDim.x + threadIdx.x;
    if (i < n) p[i] = 0.f;
}

__global__ void initP_k(float* __restrict__ P, const float* __restrict__ L, int N, int NN) {
    int i = blockIdx.x * blockDim.x + threadIdx.x;
    if (i >= 2 * NN) return;
    if (i < NN) P[i] = ((i / N) == (i % N)) ? 1.f : 0.f;
    else        P[i] = L[i - NN];
}

__global__ void split_k(const float* __restrict__ src, bf16* __restrict__ h,
                        bf16* __restrict__ l, int n) {
    int i = blockIdx.x * blockDim.x + threadIdx.x;
    if (i < n) fsplit(src[i], h[i], l[i]);
}

// PTd[(n*4+k)*N+m] = split(P[k][n][m])
__global__ void transP_split_k(const float* __restrict__ P, bf16* __restrict__ h,
                               bf16* __restrict__ l, int N, int NN) {
    int i = blockIdx.x * blockDim.x + threadIdx.x;
    if (i >= 4 * NN) return;
    int k = i / NN, r = i - k * NN;
    int n = r / N,  m = r - n * N;
    int o = (n * 4 + k) * N + m;
    fsplit(P[i], h[o], l[o]);
}

// decoder weight cat: Wc[f][k*F+o] = w[k][f][o]   (w is (4,Fin,F))
__global__ void wcat_split_k(const float* __restrict__ w, bf16* __restrict__ h,
                             bf16* __restrict__ l, int Fin, int F) {
    int tot = 4 * Fin * F;
    int i = blockIdx.x * blockDim.x + threadIdx.x;
    if (i >= tot) return;
    int k = i / (Fin * F), r = i - k * Fin * F;
    int f = r / F, o = r - f * F;
    int d = f * 4 * F + k * F + o;
    fsplit(w[i], h[d], l[d]);
}

// x (4,8,64,768) -> X dual (768, 256, 8)
__global__ void permute_in_split_k(const float* __restrict__ x, bf16* __restrict__ h,
                                   bf16* __restrict__ l) {
    int i = blockIdx.x * blockDim.x + threadIdx.x;
    if (i >= 768 * 256 * 8) return;
    int n = i >> 11;
    int rem = i & 2047;
    int bb = rem >> 3;
    int c  = rem & 7;
    int b  = bb >> 6, hw = bb & 63;
    fsplit(x[(((b * 8 + c) * 64) + hw) * 768 + n], h[i], l[i]);
}

__global__ void permute_out_k(const float* __restrict__ Fm, float* __restrict__ out) {
    int i = blockIdx.x * blockDim.x + threadIdx.x;
    if (i >= 196608) return;
    int bb = i / 768, n = i - bb * 768;
    out[i] = Fm[n * 256 + bb];
}

// healpix 4:1 max pool, dual
__global__ void pool_k(const bf16* __restrict__ sh, const bf16* __restrict__ sl,
                       bf16* __restrict__ dh, bf16* __restrict__ dl, int Np, int F) {
    int i = blockIdx.x * blockDim.x + threadIdx.x;
    int rowsz = BB * F;
    int tot = Np * rowsz;
    if (i >= tot) return;
    int n4 = i / rowsz, rem = i - n4 * rowsz;
    int base = (4 * n4) * rowsz + rem;
    int best = base;
    float bv = dread(sh, sl, base);
    #pragma unroll
    for (int j = 1; j < 4; j++) {
        int o = base + j * rowsz;
        float v = dread(sh, sl, o);
        if (v > bv) { bv = v; best = o; }
    }
    dh[i] = sh[best];
    dl[i] = sl[best];
}

// dst (N,BB,Fa+Fb) = concat(unpool(H (N/4,BB,Fa)), S (N,BB,Fb)), dual
__global__ void concat_k(const bf16* __restrict__ Hh, const bf16* __restrict__ Hl,
                         const bf16* __restrict__ Sh, const bf16* __restrict__ Sl,
                         bf16* __restrict__ dh, bf16* __restrict__ dl,
                         int N, int Fa, int Fb) {
    int Ft = Fa + Fb;
    int i = blockIdx.x * blockDim.x + threadIdx.x;
    int tot = N * BB * Ft;
    if (i >= tot) return;
    int n = i / (BB * Ft);
    int rem = i - n * (BB * Ft);
    int bb = rem / Ft;
    int f  = rem - bb * Ft;
    int s;
    if (f < Fa) {
        s = ((n >> 2) * BB + bb) * Fa + f;
        dh[i] = Hh[s]; dl[i] = Hl[s];
    } else {
        s = (n * BB + bb) * Fb + (f - Fa);
        dh[i] = Sh[s]; dl[i] = Sl[s];
    }
}

// BN stats over dual input
__global__ void bn_stats_k(const bf16* __restrict__ Yh, const bf16* __restrict__ Yl,
                           int R, int F, float* __restrict__ ST) {
    __shared__ float ssum[256];
    __shared__ float ssq [256];
    int tx = threadIdx.x, ty = threadIdx.y;
    int tid = ty * F + tx;
    int rpb = (R + gridDim.x - 1) / gridDim.x;
    int r0 = blockIdx.x * rpb;
    int r1 = imin(R, r0 + rpb);
    float s = 0.f, q = 0.f;
    for (int r = r0 + ty; r < r1; r += blockDim.y) {
        float v = dread(Yh, Yl, r * F + tx);
        s += v; q += v * v;
    }
    ssum[tid] = s; ssq[tid] = q;
    __syncthreads();
    if (ty == 0) {
        for (int yy = 1; yy < blockDim.y; yy++) {
            s += ssum[yy * F + tx];
            q += ssq [yy * F + tx];
        }
        atomicAdd(&ST[tx], s);
        atomicAdd(&ST[F + tx], q);
    }
}

__global__ void bn_apply_k(const bf16* __restrict__ sh, const bf16* __restrict__ sl,
                           bf16* __restrict__ dh, bf16* __restrict__ dl,
                           int R, int F, const float* __restrict__ ST,
                           const float* __restrict__ g, const float* __restrict__ b) {
    int i = blockIdx.x * blockDim.x + threadIdx.x;
    int tot = R * F;
    if (i >= tot) return;
    int f = i % F;
    float m = (float)R;
    float mu = ST[f] / m;
    float var = ST[F + f] / m - mu * mu;
    float v = (dread(sh, sl, i) - mu) * rsqrtf(var + 1e-5f) * g[f] + b[f];
    v = v > 0.f ? v : 0.f;
    fsplit(v, dh[i], dl[i]);
}

// ---------------- host helpers ----------------
template<typename T> static void* symv(T& s) {
    void* p = nullptr;
    cudaGetSymbolAddress(&p, s);
    return p;
}

static int ilog2(int v) { int l = 0; while ((1 << l) < v) l++; return l; }

static void gemm_f32(int M, int Nc, int K, const float* A, int lda, const float* B, int ldb,
                     float* C, int ldc, const float* D, float alpha, float beta) {
    dim3 g((Nc + 63) / 64, (M + 63) / 64, 1), b(16, 16);
    gemm_f32k<<<g, b>>>(M, Nc, K, A, lda, B, ldb, C, ldc, D, alpha, beta);
}

static void gtc_dual(int M, int Nc, int K, const bf16* Ah, const bf16* Al, int lda,
                     const bf16* Bh, const bf16* Bl, int ldb,
                     bf16* Ch, bf16* Cl, int ldc) {
    dim3 g((Nc + 63) / 64, (M + 127) / 128, 1);
    gemm_tc2<0, 1, false><<<g, 256>>>(M, Nc, K, Ah, Al, lda, Bh, Bl, ldb,
                                      Ch, Cl, nullptr, ldc, 0, 0, 0, 0, 0);
}

static void gtc_gather(int M, int Nc, int Fin, const bf16* Ah, const bf16* Al, int strideK,
                       const bf16* Bh, const bf16* Bl, bf16* Ch, bf16* Cl) {
    int K = 4 * Fin;
    dim3 g((Nc + 63) / 64, (M + 127) / 128, 1);
    gemm_tc2<1, 1, false><<<g, 256>>>(M, Nc, K, Ah, Al, 0, Bh, Bl, Nc,
                                      Ch, Cl, nullptr, Nc, Fin, ilog2(Fin), strideK, 0, 0);
}

static void gtc_scatter(int M, int Nc, int K, const bf16* Ah, const bf16* Al, int lda,
                        const bf16* Bh, const bf16* Bl, int ldb,
                        bf16* Ch, bf16* Cl, int lgF, int scPlane) {
    dim3 g((Nc + 63) / 64, (M + 127) / 128, 1);
    gemm_tc2<0, 1, true><<<g, 256>>>(M, Nc, K, Ah, Al, lda, Bh, Bl, ldb,
                                     Ch, Cl, nullptr, 0, 0, 0, 0, lgF, scPlane);
}

static void gtc_splitk(int M, int Nc, int K, const bf16* Ah, const bf16* Al, int lda,
                       const bf16* Bh, const bf16* Bl, int ldb,
                       float* Cf, int ldc, int slices) {
    dim3 g((Nc + 63) / 64, (M + 127) / 128, slices);
    gemm_tc2<0, 2, false><<<g, 256>>>(M, Nc, K, Ah, Al, lda, Bh, Bl, ldb,
                                      nullptr, nullptr, Cf, ldc, 0, 0, 0, 0, 0);
}

static void buildP(const float* L, int N, float* P) {
    int NN = N * N;
    initP_k<<<(2 * NN + 255) / 256, 256>>>(P, L, N, NN);
    gemm_f32(N, N, N, L, N, P + NN,     N, P + 2 * NN, N, P,      2.f, -1.f);
    gemm_f32(N, N, N, L, N, P + 2 * NN, N, P + 3 * NN, N, P + NN, 2.f, -1.f);
}

// ---------------- entry point ----------------
extern "C" void kernel_launch(void* const* d_in, const int* in_sizes, int n_in,
                              void* d_out, int out_size) {
    const float* x     = (const float*)d_in[0];
    const float* L3i   = (const float*)d_in[1];
    const float* L2i   = (const float*)d_in[2];
    const float* L1i   = (const float*)d_in[3];
    const float* L0i   = (const float*)d_in[4];
    const float* w_e3a = (const float*)d_in[5];
    const float* ga_e3a= (const float*)d_in[6];
    const float* be_e3a= (const float*)d_in[7];
    const float* w_e3b = (const float*)d_in[8];
    const float* ga_e3b= (const float*)d_in[9];
    const float* be_e3b= (const float*)d_in[10];
    const float* w_e2  = (const float*)d_in[11];
    const float* ga_e2 = (const float*)d_in[12];
    const float* be_e2 = (const float*)d_in[13];
    const float* w_e1  = (const float*)d_in[14];
    const float* ga_e1 = (const float*)d_in[15];
    const float* be_e1 = (const float*)d_in[16];
    const float* w_e0  = (const float*)d_in[17];
    const float* ga_e0 = (const float*)d_in[18];
    const float* be_e0 = (const float*)d_in[19];
    const float* w_d1  = (const float*)d_in[20];
    const float* ga_d1 = (const float*)d_in[21];
    const float* be_d1 = (const float*)d_in[22];
    const float* w_d2  = (const float*)d_in[23];
    const float* ga_d2 = (const float*)d_in[24];
    const float* be_d2 = (const float*)d_in[25];
    const float* w_d3  = (const float*)d_in[26];
    const float* ga_d3 = (const float*)d_in[27];
    const float* be_d3 = (const float*)d_in[28];
    const float* w_out = (const float*)d_in[29];
    float* out = (float*)d_out;

    bf16 *Xh=(bf16*)symv(g_Xh), *Xl=(bf16*)symv(g_Xl);
    bf16 *Uh=(bf16*)symv(g_Uh), *Ul=(bf16*)symv(g_Ul);
    bf16 *Yh=(bf16*)symv(g_Yh), *Yl=(bf16*)symv(g_Yl);
    bf16 *S3h=(bf16*)symv(g_S3h), *S3l=(bf16*)symv(g_S3l);
    bf16 *S2h=(bf16*)symv(g_S2h), *S2l=(bf16*)symv(g_S2l);
    bf16 *S1h=(bf16*)symv(g_S1h), *S1l=(bf16*)symv(g_S1l);
    bf16 *Wh=(bf16*)symv(g_Wh), *Wl=(bf16*)symv(g_Wl);
    bf16 *P3h=(bf16*)symv(g_P3dh), *P3l=(bf16*)symv(g_P3dl);
    bf16 *PT3h=(bf16*)symv(g_PT3dh), *PT3l=(bf16*)symv(g_PT3dl);
    bf16 *P2h=(bf16*)symv(g_P2dh), *P2l=(bf16*)symv(g_P2dl);
    bf16 *PT2h=(bf16*)symv(g_PT2dh), *PT2l=(bf16*)symv(g_PT2dl);
    bf16 *P1h=(bf16*)symv(g_P1dh), *P1l=(bf16*)symv(g_P1dl);
    bf16 *PT1h=(bf16*)symv(g_PT1dh), *PT1l=(bf16*)symv(g_PT1dl);
    bf16 *P0h=(bf16*)symv(g_P0dh), *P0l=(bf16*)symv(g_P0dl);
    float *P3=(float*)symv(g_P3), *P2=(float*)symv(g_P2);
    float *P1=(float*)symv(g_P1), *P0=(float*)symv(g_P0);
    float *Fo=(float*)symv(g_F), *ST=(float*)symv(g_ST);

    // ---- P3 + first layer front-loaded so ncu -s 5 samples the U-GEMM ----
    buildP(L3i, 768, P3);                                        // launches 0..2
    split_k<<<(2359296 + 255) / 256, 256>>>(P3, P3h, P3l, 2359296);  // 3
    permute_in_split_k<<<(768 * 256 * 8 + 255) / 256, 256>>>(x, Xh, Xl); // 4

    // e3a: U = P3stack @ X  (launch 5 — profiled)
    gtc_dual(4 * 768, BB * 8, 768, P3h, P3l, 768, Xh, Xl, BB * 8, Uh, Ul, BB * 8);
    split_k<<<(4 * 8 * 32 + 255) / 256, 256>>>(w_e3a, Wh, Wl, 4 * 8 * 32);
    gtc_gather(768 * BB, 32, 8, Uh, Ul, 768 * BB * 8, Wh, Wl, Yh, Yl);
    {   // bn e3a -> X
        zero_k<<<1, 512>>>(ST, 64);
        dim3 blk(32, 8);
        bn_stats_k<<<512, blk>>>(Yh, Yl, 768 * BB, 32, ST);
        bn_apply_k<<<(768 * BB * 32 + 255) / 256, 256>>>(Yh, Yl, Xh, Xl,
                                                         768 * BB, 32, ST, ga_e3a, be_e3a);
    }

    // remaining P builds + transposed duals
    transP_split_k<<<(2359296 + 255) / 256, 256>>>(P3, PT3h, PT3l, 768, 589824);
    buildP(L2i, 192, P2);
    split_k<<<(147456 + 255) / 256, 256>>>(P2, P2h, P2l, 147456);
    transP_split_k<<<(147456 + 255) / 256, 256>>>(P2, PT2h, PT2l, 192, 36864);
    buildP(L1i, 48, P1);
    split_k<<<(9216 + 255) / 256, 256>>>(P1, P1h, P1l, 9216);
    transP_split_k<<<(9216 + 255) / 256, 256>>>(P1, PT1h, PT1l, 48, 2304);
    buildP(L0i, 12, P0);
    split_k<<<(576 + 255) / 256, 256>>>(P0, P0h, P0l, 576);

    // ---- e3b ----
    gtc_dual(4 * 768, BB * 32, 768, P3h, P3l, 768, Xh, Xl, BB * 32, Uh, Ul, BB * 32);
    split_k<<<(4 * 32 * 64 + 255) / 256, 256>>>(w_e3b, Wh, Wl, 4 * 32 * 64);
    gtc_gather(768 * BB, 64, 32, Uh, Ul, 768 * BB * 32, Wh, Wl, Yh, Yl);
    zero_k<<<1, 512>>>(ST, 128);
    { dim3 blk(64, 4); bn_stats_k<<<512, blk>>>(Yh, Yl, 768 * BB, 64, ST); }
    bn_apply_k<<<(768 * BB * 64 + 255) / 256, 256>>>(Yh, Yl, S3h, S3l,
                                                     768 * BB, 64, ST, ga_e3b, be_e3b);
    pool_k<<<(192 * BB * 64 + 255) / 256, 256>>>(S3h, S3l, Xh, Xl, 192, 64);

    // ---- e2 ----
    gtc_dual(4 * 192, BB * 64, 192, P2h, P2l, 192, Xh, Xl, BB * 64, Uh, Ul, BB * 64);
    split_k<<<(4 * 64 * 128 + 255) / 256, 256>>>(w_e2, Wh, Wl, 4 * 64 * 128);
    gtc_gather(192 * BB, 128, 64, Uh, Ul, 192 * BB * 64, Wh, Wl, Yh, Yl);
    zero_k<<<1, 512>>>(ST, 256);
    { dim3 blk(128, 2); bn_stats_k<<<384, blk>>>(Yh, Yl, 192 * BB, 128, ST); }
    bn_apply_k<<<(192 * BB * 128 + 255) / 256, 256>>>(Yh, Yl, S2h, S2l,
                                                      192 * BB, 128, ST, ga_e2, be_e2);
    pool_k<<<(48 * BB * 128 + 255) / 256, 256>>>(S2h, S2l, Xh, Xl, 48, 128);

    // ---- e1 ----
    gtc_dual(4 * 48, BB * 128, 48, P1h, P1l, 48, Xh, Xl, BB * 128, Uh, Ul, BB * 128);
    split_k<<<(4 * 128 * 256 + 255) / 256, 256>>>(w_e1, Wh, Wl, 4 * 128 * 256);
    gtc_gather(48 * BB, 256, 128, Uh, Ul, 48 * BB * 128, Wh, Wl, Yh, Yl);
    zero_k<<<1, 512>>>(ST, 512);
    { dim3 blk(256, 1); bn_stats_k<<<96, blk>>>(Yh, Yl, 48 * BB, 256, ST); }
    bn_apply_k<<<(48 * BB * 256 + 255) / 256, 256>>>(Yh, Yl, S1h, S1l,
                                                     48 * BB, 256, ST, ga_e1, be_e1);
    pool_k<<<(12 * BB * 256 + 255) / 256, 256>>>(S1h, S1l, Xh, Xl, 12, 256);

    // ---- e0 ----  (lda=12 takes the scalar A path via avec guard)
    gtc_dual(4 * 12, BB * 256, 12, P0h, P0l, 12, Xh, Xl, BB * 256, Uh, Ul, BB * 256);
    split_k<<<(4 * 256 * 256 + 255) / 256, 256>>>(w_e0, Wh, Wl, 4 * 256 * 256);
    gtc_gather(12 * BB, 256, 256, Uh, Ul, 12 * BB * 256, Wh, Wl, Yh, Yl);
    zero_k<<<1, 512>>>(ST, 512);
    { dim3 blk(256, 1); bn_stats_k<<<24, blk>>>(Yh, Yl, 12 * BB, 256, ST); }
    bn_apply_k<<<(12 * BB * 256 + 255) / 256, 256>>>(Yh, Yl, Yh, Yl,
                                                     12 * BB, 256, ST, ga_e0, be_e0);

    // ---- d1 ----
    concat_k<<<(48 * BB * 512 + 255) / 256, 256>>>(Yh, Yl, S1h, S1l, Xh, Xl, 48, 256, 256);
    wcat_split_k<<<(4 * 512 * 128 + 255) / 256, 256>>>(w_d1, Wh, Wl, 512, 128);
    gtc_scatter(48 * BB, 4 * 128, 512, Xh, Xl, 512, Wh, Wl, 4 * 128,
                Uh, Ul, 7, 48 * BB * 128);
    gtc_dual(48, BB * 128, 4 * 48, PT1h, PT1l, 4 * 48, Uh, Ul, BB * 128, Yh, Yl, BB * 128);
    zero_k<<<1, 512>>>(ST, 256);
    { dim3 blk(128, 2); bn_stats_k<<<96, blk>>>(Yh, Yl, 48 * BB, 128, ST); }
    bn_apply_k<<<(48 * BB * 128 + 255) / 256, 256>>>(Yh, Yl, Yh, Yl,
                                                     48 * BB, 128, ST, ga_d1, be_d1);

    // ---- d2 ----
    concat_k<<<(192 * BB * 256 + 255) / 256, 256>>>(Yh, Yl, S2h, S2l, Xh, Xl, 192, 128, 128);
    wcat_split_k<<<(4 * 256 * 64 + 255) / 256, 256>>>(w_d2, Wh, Wl, 256, 64);
    gtc_scatter(192 * BB, 4 * 64, 256, Xh, Xl, 256, Wh, Wl, 4 * 64,
                Uh, Ul, 6, 192 * BB * 64);
    gtc_dual(192, BB * 64, 4 * 192, PT2h, PT2l, 4 * 192, Uh, Ul, BB * 64, Yh, Yl, BB * 64);
    zero_k<<<1, 512>>>(ST, 128);
    { dim3 blk(64, 4); bn_stats_k<<<384, blk>>>(Yh, Yl, 192 * BB, 64, ST); }
    bn_apply_k<<<(192 * BB * 64 + 255) / 256, 256>>>(Yh, Yl, Yh, Yl,
                                                     192 * BB, 64, ST, ga_d2, be_d2);

    // ---- d3 ----
    concat_k<<<(768 * BB * 128 + 255) / 256, 256>>>(Yh, Yl, S3h, S3l, Xh, Xl, 768, 64, 64);
    wcat_split_k<<<(4 * 128 * 32 + 255) / 256, 256>>>(w_d3, Wh, Wl, 128, 32);
    gtc_scatter(768 * BB, 4 * 32, 128, Xh, Xl, 128, Wh, Wl, 4 * 32,
                Uh, Ul, 5, 768 * BB * 32);
    gtc_dual(768, BB * 32, 4 * 768, PT3h, PT3l, 4 * 768, Uh, Ul, BB * 32, Yh, Yl, BB * 32);
    zero_k<<<1, 512>>>(ST, 64);
    { dim3 blk(32, 8); bn_stats_k<<<512, blk>>>(Yh, Yl, 768 * BB, 32, ST); }
    bn_apply_k<<<(768 * BB * 32 + 255) / 256, 256>>>(Yh, Yl, Yh, Yl,
                                                     768 * BB, 32, ST, ga_d3, be_d3);

    // ---- out layer ----
    wcat_split_k<<<(4 * 32 + 255) / 256, 256>>>(w_out, Wh, Wl, 32, 1);
    gtc_scatter(768 * BB, 4, 32, Yh, Yl, 32, Wh, Wl, 4, Uh, Ul, 0, 768 * BB);
    zero_k<<<(196608 + 255) / 256, 256>>>(Fo, 196608);
    gtc_splitk(768, 256, 4 * 768, PT3h, PT3l, 4 * 768, Uh, Ul, 256, Fo, 256, 8);
    permute_out_k<<<(196608 + 255) / 256, 256>>>(Fo, out);
}

// round 14
// speedup vs baseline: 2.7233x; 1.7266x over previous
#include <cuda_runtime.h>
#include <cuda_bf16.h>

#define BB 256
typedef __nv_bfloat16 bf16;

// ---------------- scratch (__device__ globals; allocation-free) ----------------
__device__ __align__(16) bf16 g_Xh[25165824], g_Xl[25165824];   // layer input dual
__device__ __align__(16) bf16 g_Uh[25165824], g_Ul[25165824];   // U / Z-stack dual
__device__ __align__(16) bf16 g_Yh[12582912], g_Yl[12582912];   // conv output dual
__device__ __align__(16) bf16 g_S3h[12582912], g_S3l[12582912];
__device__ __align__(16) bf16 g_S2h[ 6291456], g_S2l[ 6291456];
__device__ __align__(16) bf16 g_S1h[ 3145728], g_S1l[ 3145728];
__device__ __align__(16) bf16 g_Wh[262144], g_Wl[262144];
__device__ __align__(16) bf16 g_P3dh[2359296], g_P3dl[2359296];
__device__ __align__(16) bf16 g_PT3dh[2359296], g_PT3dl[2359296];
__device__ __align__(16) bf16 g_P2dh[ 147456], g_P2dl[ 147456];
__device__ __align__(16) bf16 g_PT2dh[ 147456], g_PT2dl[ 147456];
__device__ __align__(16) bf16 g_P1dh[   9216], g_P1dl[   9216];
__device__ __align__(16) bf16 g_PT1dh[   9216], g_PT1dl[   9216];
__device__ __align__(16) bf16 g_P0dh[    576], g_P0dl[    576];
__device__ __align__(16) float g_P3[2359296], g_P2[147456], g_P1[9216], g_P0[576];
__device__ __align__(16) float g_F[196608];
__device__ __align__(16) float g_ST[512];

__host__ __device__ __forceinline__ int imin(int a,int b){return a<b?a:b;}
__host__ __device__ __forceinline__ int imax(int a,int b){return a>b?a:b;}

__device__ __forceinline__ void fsplit(float x, bf16& h, bf16& l) {
    h = __float2bfloat16(x);
    l = __float2bfloat16(x - __bfloat162float(h));
}
__device__ __forceinline__ float dread(const bf16* __restrict__ H,
                                       const bf16* __restrict__ L, int i) {
    return __bfloat162float(H[i]) + __bfloat162float(L[i]);
}

__device__ __forceinline__ void mma_bf16(float* c, const unsigned* a, const unsigned* b) {
    asm volatile(
      "mma.sync.aligned.m16n8k16.row.col.f32.bf16.bf16.f32 "
      "{%0,%1,%2,%3},{%4,%5,%6,%7},{%8,%9},{%0,%1,%2,%3};"
      : "+f"(c[0]), "+f"(c[1]), "+f"(c[2]), "+f"(c[3])
      : "r"(a[0]), "r"(a[1]), "r"(a[2]), "r"(a[3]), "r"(b[0]), "r"(b[1]));
}

__device__ __forceinline__ void ldsm4(unsigned* r, const void* p) {
    unsigned a = (unsigned)__cvta_generic_to_shared(p);
    asm volatile("ldmatrix.sync.aligned.m8n8.x4.shared.b16 {%0,%1,%2,%3}, [%4];"
                 : "=r"(r[0]), "=r"(r[1]), "=r"(r[2]), "=r"(r[3]) : "r"(a));
}
__device__ __forceinline__ void ldsm4t(unsigned* r, const void* p) {
    unsigned a = (unsigned)__cvta_generic_to_shared(p);
    asm volatile("ldmatrix.sync.aligned.m8n8.x4.trans.shared.b16 {%0,%1,%2,%3}, [%4];"
                 : "=r"(r[0]), "=r"(r[1]), "=r"(r[2]), "=r"(r[3]) : "r"(a));
}

__device__ __forceinline__ void cpasync16(void* dst, const void* src, int sz) {
    unsigned sa = (unsigned)__cvta_generic_to_shared(dst);
    asm volatile("cp.async.cg.shared.global [%0], [%1], 16, %2;"
                 :: "r"(sa), "l"(src), "r"(sz));
}
__device__ __forceinline__ void cpcommit() { asm volatile("cp.async.commit_group;"); }
template<int N> __device__ __forceinline__ void cpwait() {
    asm volatile("cp.async.wait_group %0;" :: "n"(N));
}

// ================= dual-bf16 tensor-core GEMM (cp.async + ldmatrix) =================
// Logical: C = A@B with near-fp32 precision via AhBh + AhBl + AlBh
// AMODE 0: A[r*lda + k] ; AMODE 1: A[(k>>lgfin)*strideK + r*fin + (k&(fin-1))]
// EMODE 1: dual bf16 out (Ch/Cl) ; EMODE 2: split-K fp32 atomicAdd into Cf
// SCATTER (with EMODE1): col c -> addr (c>>lgF)*scPlane + r*Fsc + (c&(Fsc-1))
// SMEM: A[stage][plane] 128 rows x 32 k, 16B-chunk swizzle (kq + row/2)&3
//       B[stage][plane]  32 k   x 64 n, 16B-chunk swizzle  nq ^ (k&7)
template<int AMODE, int EMODE, bool SCATTER>
__global__ void __launch_bounds__(256, 2)
gemm_tc3(int M, int Nc, int K,
         const bf16* __restrict__ Ah_, const bf16* __restrict__ Al_, int lda,
         const bf16* __restrict__ Bh_, const bf16* __restrict__ Bl_, int ldb,
         bf16* __restrict__ Ch, bf16* __restrict__ Cl,
         float* __restrict__ Cf, int ldc,
         int fin, int lgfin, int strideK, int lgF, int scPlane)
{
    __shared__ __align__(16) bf16 sA[2][2][4096];   // 32KB
    __shared__ __align__(16) bf16 sB[2][2][2048];   // 16KB

    const int row0 = blockIdx.y << 7;
    const int col0 = blockIdx.x << 6;
    const int tid  = threadIdx.x;
    const int warp = tid >> 5, lane = tid & 31;
    const int m_w  = (warp >> 1) << 5;
    const int n_w  = (warp &  1) << 5;
    const int g    = lane >> 2, tg = lane & 3;

    int kb = 0, ke = K;
    if (EMODE == 2) {
        int ks = (((K + (int)gridDim.z - 1) / (int)gridDim.z) + 31) & ~31;
        kb = blockIdx.z * ks;
        ke = imin(K, kb + ks);
        if (kb >= ke) return;
    }

    const bool avec = (AMODE == 1) || ((lda & 7) == 0);
    const bool bvec = ((ldb & 7) == 0);

    float acc[2][4][4] = {};

    const bf16* Asrc[2] = {Ah_, Al_};
    const bf16* Bsrc[2] = {Bh_, Bl_};

    auto stage = [&](int kt, int sb) {
        // ---- A: per plane 512 x 16B chunks; 2 per thread ----
        #pragma unroll
        for (int p = 0; p < 2; p++) {
            #pragma unroll
            for (int i = 0; i < 2; i++) {
                int c = tid + (i << 8);
                int row = c >> 2, kq = c & 3;
                int gr = row0 + row, k8 = kt + (kq << 3);
                bf16* dst = &sA[sb][p][(row << 5) + (((kq + (row >> 1)) & 3) << 3)];
                if (avec) {
                    int sz = 0;
                    const bf16* src = Asrc[p];
                    if (gr < M && k8 < ke) {
                        sz = imin(8, ke - k8) * 2;
                        int addr = (AMODE == 0) ? gr * lda + k8
                                 : (k8 >> lgfin) * strideK + gr * fin + (k8 & (fin - 1));
                        src = Asrc[p] + addr;
                    }
                    cpasync16(dst, src, sz);
                } else {
                    #pragma unroll
                    for (int j = 0; j < 8; j++) {
                        int k = k8 + j;
                        bf16 v = __float2bfloat16(0.f);
                        if (gr < M && k < ke) {
                            int addr = (AMODE == 0) ? gr * lda + k
                                     : (k >> lgfin) * strideK + gr * fin + (k & (fin - 1));
                            v = Asrc[p][addr];
                        }
                        dst[j] = v;
                    }
                }
            }
        }
        // ---- B: per plane 256 x 16B chunks (row-major [k][n]); 1 per thread ----
        #pragma unroll
        for (int p = 0; p < 2; p++) {
            int krow = tid >> 3, nq = tid & 7;
            int gk = kt + krow, gc0 = col0 + (nq << 3);
            bf16* dst = &sB[sb][p][(krow << 6) + ((nq ^ (krow & 7)) << 3)];
            if (bvec) {
                int sz = 0;
                const bf16* src = Bsrc[p];
                if (gk < ke && gc0 < Nc) {
                    sz = imin(8, Nc - gc0) * 2;
                    src = Bsrc[p] + gk * ldb + gc0;
                }
                cpasync16(dst, src, sz);
            } else {
                #pragma unroll
                for (int j = 0; j < 8; j++) {
                    int gc = gc0 + j;
                    bf16 v = (gk < ke && gc < Nc) ? Bsrc[p][gk * ldb + gc]
                                                  : __float2bfloat16(0.f);
                    dst[j] = v;
                }
            }
        }
    };

    const int nt = (ke - kb + 31) >> 5;
    stage(kb, 0);
    cpcommit();

    for (int t = 0; t < nt; t++) {
        int kt = kb + (t << 5);
        if (t + 1 < nt) {
            stage(kt + 32, (t + 1) & 1);
            cpcommit();
            cpwait<1>();
        } else {
            cpwait<0>();
        }
        __syncthreads();

        int sb = t & 1;
        #pragma unroll
        for (int s = 0; s < 2; s++) {
            unsigned ah[2][4], al[2][4], bh[2][4], bl[2][4];
            // A fragments: rows = l&15, k half = (l>>4)*8
            int arow = lane & 15;
            int kc = (s << 1) + (lane >> 4);   // logical 16B chunk index 0..3
            #pragma unroll
            for (int mi = 0; mi < 2; mi++) {
                int r = m_w + (mi << 4) + arow;
                int off = (r << 5) + (((kc + (r >> 1)) & 3) << 3);
                ldsm4(ah[mi], &sA[sb][0][off]);
                ldsm4(al[mi], &sA[sb][1][off]);
            }
            // B fragments (.trans): k row = s*16 + (l&7) + ((l>>3)&1)*8 ; n half = (l>>4)*8
            int kr  = (s << 4) + (lane & 7) + (((lane >> 3) & 1) << 3);
            int nqb = (n_w >> 3) + ((lane >> 4) & 1);
            #pragma unroll
            for (int nip = 0; nip < 2; nip++) {
                int nq = nqb + (nip << 1);
                int off = (kr << 6) + ((nq ^ (kr & 7)) << 3);
                ldsm4t(bh[nip], &sB[sb][0][off]);
                ldsm4t(bl[nip], &sB[sb][1][off]);
            }
            #pragma unroll
            for (int mi = 0; mi < 2; mi++)
                #pragma unroll
                for (int ni = 0; ni < 4; ni++) {
                    unsigned bhx[2] = {bh[ni >> 1][(ni & 1) * 2], bh[ni >> 1][(ni & 1) * 2 + 1]};
                    unsigned blx[2] = {bl[ni >> 1][(ni & 1) * 2], bl[ni >> 1][(ni & 1) * 2 + 1]};
                    mma_bf16(acc[mi][ni], ah[mi], bhx);
                    mma_bf16(acc[mi][ni], ah[mi], blx);
                    mma_bf16(acc[mi][ni], al[mi], bhx);
                }
        }
        __syncthreads();
    }

    // ---- epilogue ----
    const int Fsc = 1 << lgF;
    #pragma unroll
    for (int mi = 0; mi < 2; mi++)
        #pragma unroll
        for (int ni = 0; ni < 4; ni++) {
            int gc = col0 + n_w + ni * 8 + 2 * tg;
            const float* cp = acc[mi][ni];
            #pragma unroll
            for (int h = 0; h < 2; h++) {
                int r = row0 + m_w + mi * 16 + g + h * 8;
                if (r >= M) continue;
                float v0 = cp[2 * h], v1 = cp[2 * h + 1];
                if (EMODE == 2) {
                    if (gc < Nc)     atomicAdd(&Cf[r * ldc + gc], v0);
                    if (gc + 1 < Nc) atomicAdd(&Cf[r * ldc + gc + 1], v1);
                } else if (SCATTER) {
                    if (gc < Nc) {
                        int a = (gc >> lgF) * scPlane + r * Fsc + (gc & (Fsc - 1));
                        fsplit(v0, Ch[a], Cl[a]);
                    }
                    if (gc + 1 < Nc) {
                        int c1 = gc + 1;
                        int a = (c1 >> lgF) * scPlane + r * Fsc + (c1 & (Fsc - 1));
                        fsplit(v1, Ch[a], Cl[a]);
                    }
                } else {
                    if (gc >= Nc) continue;   // Nc even in all dual uses
                    __nv_bfloat162 th, tl;
                    fsplit(v0, th.x, tl.x);
                    fsplit(v1, th.y, tl.y);
                    int o = r * ldc + gc;
                    *(__nv_bfloat162*)&Ch[o] = th;
                    *(__nv_bfloat162*)&Cl[o] = tl;
                }
            }
        }
}

// ---------------- fp32 SIMT GEMM (buildP only): C = alpha*A@B + beta*D ----------------
__global__ void __launch_bounds__(256)
gemm_f32k(int M, int Nc, int K,
          const float* __restrict__ A, int lda,
          const float* __restrict__ B, int ldb,
          float* __restrict__ C, int ldc,
          const float* __restrict__ D, float alpha, float beta)
{
    __shared__ float As[16][65];
    __shared__ float Bs[16][65];
    const int row0 = blockIdx.y << 6;
    const int col0 = blockIdx.x << 6;
    const int tid  = threadIdx.y * 16 + threadIdx.x;
    float acc[4][4] = {};
    for (int kt = 0; kt < K; kt += 16) {
        #pragma unroll
        for (int l = 0; l < 4; l++) {
            int e = tid + (l << 8);
            int m = e >> 4, kk = e & 15;
            int gr = row0 + m, gk = kt + kk;
            As[kk][m] = (gr < M && gk < K) ? A[gr * lda + gk] : 0.f;
        }
        #pragma unroll
        for (int l = 0; l < 4; l++) {
            int e = tid + (l << 8);
            int kk = e >> 6, n = e & 63;
            int gk = kt + kk, gc = col0 + n;
            Bs[kk][n] = (gk < K && gc < Nc) ? B[gk * ldb + gc] : 0.f;
        }
        __syncthreads();
        #pragma unroll
        for (int kk = 0; kk < 16; kk++) {
            float ra[4], rb[4];
            #pragma unroll
            for (int i = 0; i < 4; i++) ra[i] = As[kk][(threadIdx.y << 2) + i];
            #pragma unroll
            for (int j = 0; j < 4; j++) rb[j] = Bs[kk][(threadIdx.x << 2) + j];
            #pragma unroll
            for (int i = 0; i < 4; i++)
                #pragma unroll
                for (int j = 0; j < 4; j++)
                    acc[i][j] += ra[i] * rb[j];
        }
        __syncthreads();
    }
    #pragma unroll
    for (int i = 0; i < 4; i++) {
        int gr = row0 + (threadIdx.y << 2) + i;
        if (gr >= M) continue;
        #pragma unroll
        for (int j = 0; j < 4; j++) {
            int gc = col0 + (threadIdx.x << 2) + j;
            if (gc >= Nc) continue;
            float v = alpha * acc[i][j];
            if (D != nullptr) v += beta * D[gr * ldc + gc];
            C[gr * ldc + gc] = v;
        }
    }
}

// ---------------- small kernels ----------------
__global__ void zero_k(float* p, int n) {
    int i = blockIdx.x * blockDim.x + threadIdx.x;
    if (i < n) p[i] = 0.f;
}

__global__ void initP_k(float* __restrict__ P, const float* __restrict__ L, int N, int NN) {
    int i = blockIdx.x * blockDim.x + threadIdx.x;
    if (i >= 2 * NN) return;
    if (i < NN) P[i] = ((i / N) == (i % N)) ? 1.f : 0.f;
    else        P[i] = L[i - NN];
}

__global__ void split_k(const float* __restrict__ src, bf16* __restrict__ h,
                        bf16* __restrict__ l, int n) {
    int i = blockIdx.x * blockDim.x + threadIdx.x;
    if (i < n) fsplit(src[i], h[i], l[i]);
}

// PTd[(n*4+k)*N+m] = split(P[k][n][m])
__global__ void transP_split_k(const float* __restrict__ P, bf16* __restrict__ h,
                               bf16* __restrict__ l, int N, int NN) {
    int i = blockIdx.x * blockDim.x + threadIdx.x;
    if (i >= 4 * NN) return;
    int k = i / NN, r = i - k * NN;
    int n = r / N,  m = r - n * N;
    int o = (n * 4 + k) * N + m;
    fsplit(P[i], h[o], l[o]);
}

// decoder weight cat: Wc[f][k*F+o] = w[k][f][o]   (w is (4,Fin,F))
__global__ void wcat_split_k(const float* __restrict__ w, bf16* __restrict__ h,
                             bf16* __restrict__ l, int Fin, int F) {
    int tot = 4 * Fin * F;
    int i = blockIdx.x * blockDim.x + threadIdx.x;
    if (i >= tot) return;
    int k = i / (Fin * F), r = i - k * Fin * F;
    int f = r / F, o = r - f * F;
    int d = f * 4 * F + k * F + o;
    fsplit(w[i], h[d], l[d]);
}

// x (4,8,64,768) -> X dual (768, 256, 8)
__global__ void permute_in_split_k(const float* __restrict__ x, bf16* __restrict__ h,
                                   bf16* __restrict__ l) {
    int i = blockIdx.x * blockDim.x + threadIdx.x;
    if (i >= 768 * 256 * 8) return;
    int n = i >> 11;
    int rem = i & 2047;
    int bb = rem >> 3;
    int c  = rem & 7;
    int b  = bb >> 6, hw = bb & 63;
    fsplit(x[(((b * 8 + c) * 64) + hw) * 768 + n], h[i], l[i]);
}

__global__ void permute_out_k(const float* __restrict__ Fm, float* __restrict__ out) {
    int i = blockIdx.x * blockDim.x + threadIdx.x;
    if (i >= 196608) return;
    int bb = i / 768, n = i - bb * 768;
    out[i] = Fm[n * 256 + bb];
}

// healpix 4:1 max pool, dual
__global__ void pool_k(const bf16* __restrict__ sh, const bf16* __restrict__ sl,
                       bf16* __restrict__ dh, bf16* __restrict__ dl, int Np, int F) {
    int i = blockIdx.x * blockDim.x + threadIdx.x;
    int rowsz = BB * F;
    int tot = Np * rowsz;
    if (i >= tot) return;
    int n4 = i / rowsz, rem = i - n4 * rowsz;
    int base = (4 * n4) * rowsz + rem;
    int best = base;
    float bv = dread(sh, sl, base);
    #pragma unroll
    for (int j = 1; j < 4; j++) {
        int o = base + j * rowsz;
        float v = dread(sh, sl, o);
        if (v > bv) { bv = v; best = o; }
    }
    dh[i] = sh[best];
    dl[i] = sl[best];
}

// dst (N,BB,Fa+Fb) = concat(unpool(H (N/4,BB,Fa)), S (N,BB,Fb)), dual
__global__ void concat_k(const bf16* __restrict__ Hh, const bf16* __restrict__ Hl,
                         const bf16* __restrict__ Sh, const bf16* __restrict__ Sl,
                         bf16* __restrict__ dh, bf16* __restrict__ dl,
                         int N, int Fa, int Fb) {
    int Ft = Fa + Fb;
    int i = blockIdx.x * blockDim.x + threadIdx.x;
    int tot = N * BB * Ft;
    if (i >= tot) return;
    int n = i / (BB * Ft);
    int rem = i - n * (BB * Ft);
    int bb = rem / Ft;
    int f  = rem - bb * Ft;
    int s;
    if (f < Fa) {
        s = ((n >> 2) * BB + bb) * Fa + f;
        dh[i] = Hh[s]; dl[i] = Hl[s];
    } else {
        s = (n * BB + bb) * Fb + (f - Fa);
        dh[i] = Sh[s]; dl[i] = Sl[s];
    }
}

// BN stats over dual input
__global__ void bn_stats_k(const bf16* __restrict__ Yh, const bf16* __restrict__ Yl,
                           int R, int F, float* __restrict__ ST) {
    __shared__ float ssum[256];
    __shared__ float ssq [256];
    int tx = threadIdx.x, ty = threadIdx.y;
    int tid = ty * F + tx;
    int rpb = (R + gridDim.x - 1) / gridDim.x;
    int r0 = blockIdx.x * rpb;
    int r1 = imin(R, r0 + rpb);
    float s = 0.f, q = 0.f;
    for (int r = r0 + ty; r < r1; r += blockDim.y) {
        float v = dread(Yh, Yl, r * F + tx);
        s += v; q += v * v;
    }
    ssum[tid] = s; ssq[tid] = q;
    __syncthreads();
    if (ty == 0) {
        for (int yy = 1; yy < blockDim.y; yy++) {
            s += ssum[yy * F + tx];
            q += ssq [yy * F + tx];
        }
        atomicAdd(&ST[tx], s);
        atomicAdd(&ST[F + tx], q);
    }
}

__global__ void bn_apply_k(const bf16* __restrict__ sh, const bf16* __restrict__ sl,
                           bf16* __restrict__ dh, bf16* __restrict__ dl,
                           int R, int F, const float* __restrict__ ST,
                           const float* __restrict__ g, const float* __restrict__ b) {
    int i = blockIdx.x * blockDim.x + threadIdx.x;
    int tot = R * F;
    if (i >= tot) return;
    int f = i % F;
    float m = (float)R;
    float mu = ST[f] / m;
    float var = ST[F + f] / m - mu * mu;
    float v = (dread(sh, sl, i) - mu) * rsqrtf(var + 1e-5f) * g[f] + b[f];
    v = v > 0.f ? v : 0.f;
    fsplit(v, dh[i], dl[i]);
}

// ---------------- host helpers ----------------
template<typename T> static void* symv(T& s) {
    void* p = nullptr;
    cudaGetSymbolAddress(&p, s);
    return p;
}

static int ilog2(int v) { int l = 0; while ((1 << l) < v) l++; return l; }

static void gemm_f32(int M, int Nc, int K, const float* A, int lda, const float* B, int ldb,
                     float* C, int ldc, const float* D, float alpha, float beta) {
    dim3 g((Nc + 63) / 64, (M + 63) / 64, 1), b(16, 16);
    gemm_f32k<<<g, b>>>(M, Nc, K, A, lda, B, ldb, C, ldc, D, alpha, beta);
}

static void gtc_dual(int M, int Nc, int K, const bf16* Ah, const bf16* Al, int lda,
                     const bf16* Bh, const bf16* Bl, int ldb,
                     bf16* Ch, bf16* Cl, int ldc) {
    dim3 g((Nc + 63) / 64, (M + 127) / 128, 1);
    gemm_tc3<0, 1, false><<<g, 256>>>(M, Nc, K, Ah, Al, lda, Bh, Bl, ldb,
                                      Ch, Cl, nullptr, ldc, 0, 0, 0, 0, 0);
}

static void gtc_gather(int M, int Nc, int Fin, const bf16* Ah, const bf16* Al, int strideK,
                       const bf16* Bh, const bf16* Bl, bf16* Ch, bf16* Cl) {
    int K = 4 * Fin;
    dim3 g((Nc + 63) / 64, (M + 127) / 128, 1);
    gemm_tc3<1, 1, false><<<g, 256>>>(M, Nc, K, Ah, Al, 0, Bh, Bl, Nc,
                                      Ch, Cl, nullptr, Nc, Fin, ilog2(Fin), strideK, 0, 0);
}

static void gtc_scatter(int M, int Nc, int K, const bf16* Ah, const bf16* Al, int lda,
                        const bf16* Bh, const bf16* Bl, int ldb,
                        bf16* Ch, bf16* Cl, int lgF, int scPlane) {
    dim3 g((Nc + 63) / 64, (M + 127) / 128, 1);
    gemm_tc3<0, 1, true><<<g, 256>>>(M, Nc, K, Ah, Al, lda, Bh, Bl, ldb,
                                     Ch, Cl, nullptr, 0, 0, 0, 0, lgF, scPlane);
}

static void gtc_splitk(int M, int Nc, int K, const bf16* Ah, const bf16* Al, int lda,
                       const bf16* Bh, const bf16* Bl, int ldb,
                       float* Cf, int ldc, int slices) {
    dim3 g((Nc + 63) / 64, (M + 127) / 128, slices);
    gemm_tc3<0, 2, false><<<g, 256>>>(M, Nc, K, Ah, Al, lda, Bh, Bl, ldb,
                                      nullptr, nullptr, Cf, ldc, 0, 0, 0, 0, 0);
}

static void buildP(const float* L, int N, float* P) {
    int NN = N * N;
    initP_k<<<(2 * NN + 255) / 256, 256>>>(P, L, N, NN);
    gemm_f32(N, N, N, L, N, P + NN,     N, P + 2 * NN, N, P,      2.f, -1.f);
    gemm_f32(N, N, N, L, N, P + 2 * NN, N, P + 3 * NN, N, P + NN, 2.f, -1.f);
}

// ---------------- entry point ----------------
extern "C" void kernel_launch(void* const* d_in, const int* in_sizes, int n_in,
                              void* d_out, int out_size) {
    const float* x     = (const float*)d_in[0];
    const float* L3i   = (const float*)d_in[1];
    const float* L2i   = (const float*)d_in[2];
    const float* L1i   = (const float*)d_in[3];
    const float* L0i   = (const float*)d_in[4];
    const float* w_e3a = (const float*)d_in[5];
    const float* ga_e3a= (const float*)d_in[6];
    const float* be_e3a= (const float*)d_in[7];
    const float* w_e3b = (const float*)d_in[8];
    const float* ga_e3b= (const float*)d_in[9];
    const float* be_e3b= (const float*)d_in[10];
    const float* w_e2  = (const float*)d_in[11];
    const float* ga_e2 = (const float*)d_in[12];
    const float* be_e2 = (const float*)d_in[13];
    const float* w_e1  = (const float*)d_in[14];
    const float* ga_e1 = (const float*)d_in[15];
    const float* be_e1 = (const float*)d_in[16];
    const float* w_e0  = (const float*)d_in[17];
    const float* ga_e0 = (const float*)d_in[18];
    const float* be_e0 = (const float*)d_in[19];
    const float* w_d1  = (const float*)d_in[20];
    const float* ga_d1 = (const float*)d_in[21];
    const float* be_d1 = (const float*)d_in[22];
    const float* w_d2  = (const float*)d_in[23];
    const float* ga_d2 = (const float*)d_in[24];
    const float* be_d2 = (const float*)d_in[25];
    const float* w_d3  = (const float*)d_in[26];
    const float* ga_d3 = (const float*)d_in[27];
    const float* be_d3 = (const float*)d_in[28];
    const float* w_out = (const float*)d_in[29];
    float* out = (float*)d_out;

    bf16 *Xh=(bf16*)symv(g_Xh), *Xl=(bf16*)symv(g_Xl);
    bf16 *Uh=(bf16*)symv(g_Uh), *Ul=(bf16*)symv(g_Ul);
    bf16 *Yh=(bf16*)symv(g_Yh), *Yl=(bf16*)symv(g_Yl);
    bf16 *S3h=(bf16*)symv(g_S3h), *S3l=(bf16*)symv(g_S3l);
    bf16 *S2h=(bf16*)symv(g_S2h), *S2l=(bf16*)symv(g_S2l);
    bf16 *S1h=(bf16*)symv(g_S1h), *S1l=(bf16*)symv(g_S1l);
    bf16 *Wh=(bf16*)symv(g_Wh), *Wl=(bf16*)symv(g_Wl);
    bf16 *P3h=(bf16*)symv(g_P3dh), *P3l=(bf16*)symv(g_P3dl);
    bf16 *PT3h=(bf16*)symv(g_PT3dh), *PT3l=(bf16*)symv(g_PT3dl);
    bf16 *P2h=(bf16*)symv(g_P2dh), *P2l=(bf16*)symv(g_P2dl);
    bf16 *PT2h=(bf16*)symv(g_PT2dh), *PT2l=(bf16*)symv(g_PT2dl);
    bf16 *P1h=(bf16*)symv(g_P1dh), *P1l=(bf16*)symv(g_P1dl);
    bf16 *PT1h=(bf16*)symv(g_PT1dh), *PT1l=(bf16*)symv(g_PT1dl);
    bf16 *P0h=(bf16*)symv(g_P0dh), *P0l=(bf16*)symv(g_P0dl);
    float *P3=(float*)symv(g_P3), *P2=(float*)symv(g_P2);
    float *P1=(float*)symv(g_P1), *P0=(float*)symv(g_P0);
    float *Fo=(float*)symv(g_F), *ST=(float*)symv(g_ST);

    // ---- P3 + first layer front-loaded ----
    buildP(L3i, 768, P3);
    split_k<<<(2359296 + 255) / 256, 256>>>(P3, P3h, P3l, 2359296);
    permute_in_split_k<<<(768 * 256 * 8 + 255) / 256, 256>>>(x, Xh, Xl);

    // e3a: U = P3stack @ X
    gtc_dual(4 * 768, BB * 8, 768, P3h, P3l, 768, Xh, Xl, BB * 8, Uh, Ul, BB * 8);
    split_k<<<(4 * 8 * 32 + 255) / 256, 256>>>(w_e3a, Wh, Wl, 4 * 8 * 32);
    gtc_gather(768 * BB, 32, 8, Uh, Ul, 768 * BB * 8, Wh, Wl, Yh, Yl);
    {   // bn e3a -> X
        zero_k<<<1, 512>>>(ST, 64);
        dim3 blk(32, 8);
        bn_stats_k<<<512, blk>>>(Yh, Yl, 768 * BB, 32, ST);
        bn_apply_k<<<(768 * BB * 32 + 255) / 256, 256>>>(Yh, Yl, Xh, Xl,
                                                         768 * BB, 32, ST, ga_e3a, be_e3a);
    }

    // remaining P builds + transposed duals
    transP_split_k<<<(2359296 + 255) / 256, 256>>>(P3, PT3h, PT3l, 768, 589824);
    buildP(L2i, 192, P2);
    split_k<<<(147456 + 255) / 256, 256>>>(P2, P2h, P2l, 147456);
    transP_split_k<<<(147456 + 255) / 256, 256>>>(P2, PT2h, PT2l, 192, 36864);
    buildP(L1i, 48, P1);
    split_k<<<(9216 + 255) / 256, 256>>>(P1, P1h, P1l, 9216);
    transP_split_k<<<(9216 + 255) / 256, 256>>>(P1, PT1h, PT1l, 48, 2304);
    buildP(L0i, 12, P0);
    split_k<<<(576 + 255) / 256, 256>>>(P0, P0h, P0l, 576);

    // ---- e3b ----
    gtc_dual(4 * 768, BB * 32, 768, P3h, P3l, 768, Xh, Xl, BB * 32, Uh, Ul, BB * 32);
    split_k<<<(4 * 32 * 64 + 255) / 256, 256>>>(w_e3b, Wh, Wl, 4 * 32 * 64);
    gtc_gather(768 * BB, 64, 32, Uh, Ul, 768 * BB * 32, Wh, Wl, Yh, Yl);
    zero_k<<<1, 512>>>(ST, 128);
    { dim3 blk(64, 4); bn_stats_k<<<512, blk>>>(Yh, Yl, 768 * BB, 64, ST); }
    bn_apply_k<<<(768 * BB * 64 + 255) / 256, 256>>>(Yh, Yl, S3h, S3l,
                                                     768 * BB, 64, ST, ga_e3b, be_e3b);
    pool_k<<<(192 * BB * 64 + 255) / 256, 256>>>(S3h, S3l, Xh, Xl, 192, 64);

    // ---- e2 ----
    gtc_dual(4 * 192, BB * 64, 192, P2h, P2l, 192, Xh, Xl, BB * 64, Uh, Ul, BB * 64);
    split_k<<<(4 * 64 * 128 + 255) / 256, 256>>>(w_e2, Wh, Wl, 4 * 64 * 128);
    gtc_gather(192 * BB, 128, 64, Uh, Ul, 192 * BB * 64, Wh, Wl, Yh, Yl);
    zero_k<<<1, 512>>>(ST, 256);
    { dim3 blk(128, 2); bn_stats_k<<<384, blk>>>(Yh, Yl, 192 * BB, 128, ST); }
    bn_apply_k<<<(192 * BB * 128 + 255) / 256, 256>>>(Yh, Yl, S2h, S2l,
                                                      192 * BB, 128, ST, ga_e2, be_e2);
    pool_k<<<(48 * BB * 128 + 255) / 256, 256>>>(S2h, S2l, Xh, Xl, 48, 128);

    // ---- e1 ----
    gtc_dual(4 * 48, BB * 128, 48, P1h, P1l, 48, Xh, Xl, BB * 128, Uh, Ul, BB * 128);
    split_k<<<(4 * 128 * 256 + 255) / 256, 256>>>(w_e1, Wh, Wl, 4 * 128 * 256);
    gtc_gather(48 * BB, 256, 128, Uh, Ul, 48 * BB * 128, Wh, Wl, Yh, Yl);
    zero_k<<<1, 512>>>(ST, 512);
    { dim3 blk(256, 1); bn_stats_k<<<96, blk>>>(Yh, Yl, 48 * BB, 256, ST); }
    bn_apply_k<<<(48 * BB * 256 + 255) / 256, 256>>>(Yh, Yl, S1h, S1l,
                                                     48 * BB, 256, ST, ga_e1, be_e1);
    pool_k<<<(12 * BB * 256 + 255) / 256, 256>>>(S1h, S1l, Xh, Xl, 12, 256);

    // ---- e0 ----  (lda=12 takes the scalar A path via avec guard)
    gtc_dual(4 * 12, BB * 256, 12, P0h, P0l, 12, Xh, Xl, BB * 256, Uh, Ul, BB * 256);
    split_k<<<(4 * 256 * 256 + 255) / 256, 256>>>(w_e0, Wh, Wl, 4 * 256 * 256);
    gtc_gather(12 * BB, 256, 256, Uh, Ul, 12 * BB * 256, Wh, Wl, Yh, Yl);
    zero_k<<<1, 512>>>(ST, 512);
    { dim3 blk(256, 1); bn_stats_k<<<24, blk>>>(Yh, Yl, 12 * BB, 256, ST); }
    bn_apply_k<<<(12 * BB * 256 + 255) / 256, 256>>>(Yh, Yl, Yh, Yl,
                                                     12 * BB, 256, ST, ga_e0, be_e0);

    // ---- d1 ----
    concat_k<<<(48 * BB * 512 + 255) / 256, 256>>>(Yh, Yl, S1h, S1l, Xh, Xl, 48, 256, 256);
    wcat_split_k<<<(4 * 512 * 128 + 255) / 256, 256>>>(w_d1, Wh, Wl, 512, 128);
    gtc_scatter(48 * BB, 4 * 128, 512, Xh, Xl, 512, Wh, Wl, 4 * 128,
                Uh, Ul, 7, 48 * BB * 128);
    gtc_dual(48, BB * 128, 4 * 48, PT1h, PT1l, 4 * 48, Uh, Ul, BB * 128, Yh, Yl, BB * 128);
    zero_k<<<1, 512>>>(ST, 256);
    { dim3 blk(128, 2); bn_stats_k<<<96, blk>>>(Yh, Yl, 48 * BB, 128, ST); }
    bn_apply_k<<<(48 * BB * 128 + 255) / 256, 256>>>(Yh, Yl, Yh, Yl,
                                                     48 * BB, 128, ST, ga_d1, be_d1);

    // ---- d2 ----
    concat_k<<<(192 * BB * 256 + 255) / 256, 256>>>(Yh, Yl, S2h, S2l, Xh, Xl, 192, 128, 128);
    wcat_split_k<<<(4 * 256 * 64 + 255) / 256, 256>>>(w_d2, Wh, Wl, 256, 64);
    gtc_scatter(192 * BB, 4 * 64, 256, Xh, Xl, 256, Wh, Wl, 4 * 64,
                Uh, Ul, 6, 192 * BB * 64);
    gtc_dual(192, BB * 64, 4 * 192, PT2h, PT2l, 4 * 192, Uh, Ul, BB * 64, Yh, Yl, BB * 64);
    zero_k<<<1, 512>>>(ST, 128);
    { dim3 blk(64, 4); bn_stats_k<<<384, blk>>>(Yh, Yl, 192 * BB, 64, ST); }
    bn_apply_k<<<(192 * BB * 64 + 255) / 256, 256>>>(Yh, Yl, Yh, Yl,
                                                     192 * BB, 64, ST, ga_d2, be_d2);

    // ---- d3 ----
    concat_k<<<(768 * BB * 128 + 255) / 256, 256>>>(Yh, Yl, S3h, S3l, Xh, Xl, 768, 64, 64);
    wcat_split_k<<<(4 * 128 * 32 + 255) / 256, 256>>>(w_d3, Wh, Wl, 128, 32);
    gtc_scatter(768 * BB, 4 * 32, 128, Xh, Xl, 128, Wh, Wl, 4 * 32,
                Uh, Ul, 5, 768 * BB * 32);
    gtc_dual(768, BB * 32, 4 * 768, PT3h, PT3l, 4 * 768, Uh, Ul, BB * 32, Yh, Yl, BB * 32);
    zero_k<<<1, 512>>>(ST, 64);
    { dim3 blk(32, 8); bn_stats_k<<<512, blk>>>(Yh, Yl, 768 * BB, 32, ST); }
    bn_apply_k<<<(768 * BB * 32 + 255) / 256, 256>>>(Yh, Yl, Yh, Yl,
                                                     768 * BB, 32, ST, ga_d3, be_d3);

    // ---- out layer ----
    wcat_split_k<<<(4 * 32 + 255) / 256, 256>>>(w_out, Wh, Wl, 32, 1);
    gtc_scatter(768 * BB, 4, 32, Yh, Yl, 32, Wh, Wl, 4, Uh, Ul, 0, 768 * BB);
    zero_k<<<(196608 + 255) / 256, 256>>>(Fo, 196608);
    gtc_splitk(768, 256, 4 * 768, PT3h, PT3l, 4 * 768, Uh, Ul, 256, Fo, 256, 8);
    permute_out_k<<<(196608 + 255) / 256, 256>>>(Fo, out);
}

// round 15
// speedup vs baseline: 2.7944x; 1.0261x over previous
#include <cuda_runtime.h>
#include <cuda_bf16.h>

#define BB 256
typedef __nv_bfloat16 bf16;

// ---------------- scratch (__device__ globals; allocation-free) ----------------
__device__ __align__(16) bf16 g_Xh[25165824], g_Xl[25165824];   // layer input dual
__device__ __align__(16) bf16 g_Uh[25165824], g_Ul[25165824];   // U / Z-stack dual
__device__ __align__(16) bf16 g_Yh[12582912], g_Yl[12582912];   // conv output dual
__device__ __align__(16) bf16 g_S3h[12582912], g_S3l[12582912];
__device__ __align__(16) bf16 g_S2h[ 6291456], g_S2l[ 6291456];
__device__ __align__(16) bf16 g_S1h[ 3145728], g_S1l[ 3145728];
__device__ __align__(16) bf16 g_Wh[262144], g_Wl[262144];
__device__ __align__(16) bf16 g_P3dh[2359296], g_P3dl[2359296];
__device__ __align__(16) bf16 g_PT3dh[2359296], g_PT3dl[2359296];
__device__ __align__(16) bf16 g_P2dh[ 147456], g_P2dl[ 147456];
__device__ __align__(16) bf16 g_PT2dh[ 147456], g_PT2dl[ 147456];
__device__ __align__(16) bf16 g_P1dh[   9216], g_P1dl[   9216];
__device__ __align__(16) bf16 g_PT1dh[   9216], g_PT1dl[   9216];
__device__ __align__(16) bf16 g_P0dh[    576], g_P0dl[    576];
__device__ __align__(16) float g_P3[2359296], g_P2[147456], g_P1[9216], g_P0[576];
__device__ __align__(16) float g_F[196608];
__device__ __align__(16) float g_ST[512];

__host__ __device__ __forceinline__ int imin(int a,int b){return a<b?a:b;}
__host__ __device__ __forceinline__ int imax(int a,int b){return a>b?a:b;}

__device__ __forceinline__ void fsplit(float x, bf16& h, bf16& l) {
    h = __float2bfloat16(x);
    l = __float2bfloat16(x - __bfloat162float(h));
}
__device__ __forceinline__ float dread(const bf16* __restrict__ H,
                                       const bf16* __restrict__ L, int i) {
    return __bfloat162float(H[i]) + __bfloat162float(L[i]);
}

__device__ __forceinline__ void mma_bf16(float* c, const unsigned* a, const unsigned* b) {
    asm volatile(
      "mma.sync.aligned.m16n8k16.row.col.f32.bf16.bf16.f32 "
      "{%0,%1,%2,%3},{%4,%5,%6,%7},{%8,%9},{%0,%1,%2,%3};"
      : "+f"(c[0]), "+f"(c[1]), "+f"(c[2]), "+f"(c[3])
      : "r"(a[0]), "r"(a[1]), "r"(a[2]), "r"(a[3]), "r"(b[0]), "r"(b[1]));
}

__device__ __forceinline__ void ldsm4(unsigned* r, const void* p) {
    unsigned a = (unsigned)__cvta_generic_to_shared(p);
    asm volatile("ldmatrix.sync.aligned.m8n8.x4.shared.b16 {%0,%1,%2,%3}, [%4];"
                 : "=r"(r[0]), "=r"(r[1]), "=r"(r[2]), "=r"(r[3]) : "r"(a));
}
__device__ __forceinline__ void ldsm4t(unsigned* r, const void* p) {
    unsigned a = (unsigned)__cvta_generic_to_shared(p);
    asm volatile("ldmatrix.sync.aligned.m8n8.x4.trans.shared.b16 {%0,%1,%2,%3}, [%4];"
                 : "=r"(r[0]), "=r"(r[1]), "=r"(r[2]), "=r"(r[3]) : "r"(a));
}

__device__ __forceinline__ void cpasync16(void* dst, const void* src, int sz) {
    unsigned sa = (unsigned)__cvta_generic_to_shared(dst);
    asm volatile("cp.async.cg.shared.global [%0], [%1], 16, %2;"
                 :: "r"(sa), "l"(src), "r"(sz));
}
__device__ __forceinline__ void cpcommit() { asm volatile("cp.async.commit_group;"); }
template<int N> __device__ __forceinline__ void cpwait() {
    asm volatile("cp.async.wait_group %0;" :: "n"(N));
}

// ================= dual-bf16 tensor-core GEMM (cp.async + ldmatrix) =================
// Logical: C = A@B with near-fp32 precision via AhBh + AhBl + AlBh
// AMODE 0: A[r*lda + k] ; AMODE 1: A[(k>>lgfin)*strideK + r*fin + (k&(fin-1))]
// EMODE 1: dual bf16 out (Ch/Cl) ; EMODE 2: split-K fp32 atomicAdd into Cf
// SCATTER (with EMODE1): col c -> addr (c>>lgF)*scPlane + r*Fsc + (c&(Fsc-1))
// STp != nullptr (EMODE1): BN stats fused — per-channel sum/sumsq accumulated
//   with channel f = gc & ((1<<lgFstat)-1), smem-reduced, atomicAdd to STp.
template<int AMODE, int EMODE, bool SCATTER>
__global__ void __launch_bounds__(256, 2)
gemm_tc3(int M, int Nc, int K,
         const bf16* __restrict__ Ah_, const bf16* __restrict__ Al_, int lda,
         const bf16* __restrict__ Bh_, const bf16* __restrict__ Bl_, int ldb,
         bf16* __restrict__ Ch, bf16* __restrict__ Cl,
         float* __restrict__ Cf, int ldc,
         int fin, int lgfin, int strideK, int lgF, int scPlane,
         float* __restrict__ STp, int lgFstat)
{
    __shared__ __align__(16) bf16 sA[2][2][4096];   // 32KB
    __shared__ __align__(16) bf16 sB[2][2][2048];   // 16KB

    const int row0 = blockIdx.y << 7;
    const int col0 = blockIdx.x << 6;
    const int tid  = threadIdx.x;
    const int warp = tid >> 5, lane = tid & 31;
    const int m_w  = (warp >> 1) << 5;
    const int n_w  = (warp &  1) << 5;
    const int g    = lane >> 2, tg = lane & 3;

    int kb = 0, ke = K;
    if (EMODE == 2) {
        int ks = (((K + (int)gridDim.z - 1) / (int)gridDim.z) + 31) & ~31;
        kb = blockIdx.z * ks;
        ke = imin(K, kb + ks);
        if (kb >= ke) return;
    }

    const bool avec = (AMODE == 1) || ((lda & 7) == 0);
    const bool bvec = ((ldb & 7) == 0);

    float acc[2][4][4] = {};

    const bf16* Asrc[2] = {Ah_, Al_};
    const bf16* Bsrc[2] = {Bh_, Bl_};

    auto stage = [&](int kt, int sb) {
        #pragma unroll
        for (int p = 0; p < 2; p++) {
            #pragma unroll
            for (int i = 0; i < 2; i++) {
                int c = tid + (i << 8);
                int row = c >> 2, kq = c & 3;
                int gr = row0 + row, k8 = kt + (kq << 3);
                bf16* dst = &sA[sb][p][(row << 5) + (((kq + (row >> 1)) & 3) << 3)];
                if (avec) {
                    int sz = 0;
                    const bf16* src = Asrc[p];
                    if (gr < M && k8 < ke) {
                        sz = imin(8, ke - k8) * 2;
                        int addr = (AMODE == 0) ? gr * lda + k8
                                 : (k8 >> lgfin) * strideK + gr * fin + (k8 & (fin - 1));
                        src = Asrc[p] + addr;
                    }
                    cpasync16(dst, src, sz);
                } else {
                    #pragma unroll
                    for (int j = 0; j < 8; j++) {
                        int k = k8 + j;
                        bf16 v = __float2bfloat16(0.f);
                        if (gr < M && k < ke) {
                            int addr = (AMODE == 0) ? gr * lda + k
                                     : (k >> lgfin) * strideK + gr * fin + (k & (fin - 1));
                            v = Asrc[p][addr];
                        }
                        dst[j] = v;
                    }
                }
            }
        }
        #pragma unroll
        for (int p = 0; p < 2; p++) {
            int krow = tid >> 3, nq = tid & 7;
            int gk = kt + krow, gc0 = col0 + (nq << 3);
            bf16* dst = &sB[sb][p][(krow << 6) + ((nq ^ (krow & 7)) << 3)];
            if (bvec) {
                int sz = 0;
                const bf16* src = Bsrc[p];
                if (gk < ke && gc0 < Nc) {
                    sz = imin(8, Nc - gc0) * 2;
                    src = Bsrc[p] + gk * ldb + gc0;
                }
                cpasync16(dst, src, sz);
            } else {
                #pragma unroll
                for (int j = 0; j < 8; j++) {
                    int gc = gc0 + j;
                    bf16 v = (gk < ke && gc < Nc) ? Bsrc[p][gk * ldb + gc]
                                                  : __float2bfloat16(0.f);
                    dst[j] = v;
                }
            }
        }
    };

    const int nt = (ke - kb + 31) >> 5;
    stage(kb, 0);
    cpcommit();

    for (int t = 0; t < nt; t++) {
        int kt = kb + (t << 5);
        if (t + 1 < nt) {
            stage(kt + 32, (t + 1) & 1);
            cpcommit();
            cpwait<1>();
        } else {
            cpwait<0>();
        }
        __syncthreads();

        int sb = t & 1;
        #pragma unroll
        for (int s = 0; s < 2; s++) {
            unsigned ah[2][4], al[2][4], bh[2][4], bl[2][4];
            int arow = lane & 15;
            int kc = (s << 1) + (lane >> 4);
            #pragma unroll
            for (int mi = 0; mi < 2; mi++) {
                int r = m_w + (mi << 4) + arow;
                int off = (r << 5) + (((kc + (r >> 1)) & 3) << 3);
                ldsm4(ah[mi], &sA[sb][0][off]);
                ldsm4(al[mi], &sA[sb][1][off]);
            }
            int kr  = (s << 4) + (lane & 7) + (((lane >> 3) & 1) << 3);
            int nqb = (n_w >> 3) + ((lane >> 4) & 1);
            #pragma unroll
            for (int nip = 0; nip < 2; nip++) {
                int nq = nqb + (nip << 1);
                int off = (kr << 6) + ((nq ^ (kr & 7)) << 3);
                ldsm4t(bh[nip], &sB[sb][0][off]);
                ldsm4t(bl[nip], &sB[sb][1][off]);
            }
            #pragma unroll
            for (int mi = 0; mi < 2; mi++)
                #pragma unroll
                for (int ni = 0; ni < 4; ni++) {
                    unsigned bhx[2] = {bh[ni >> 1][(ni & 1) * 2], bh[ni >> 1][(ni & 1) * 2 + 1]};
                    unsigned blx[2] = {bl[ni >> 1][(ni & 1) * 2], bl[ni >> 1][(ni & 1) * 2 + 1]};
                    mma_bf16(acc[mi][ni], ah[mi], bhx);
                    mma_bf16(acc[mi][ni], ah[mi], blx);
                    mma_bf16(acc[mi][ni], al[mi], bhx);
                }
        }
        __syncthreads();
    }

    // ---- epilogue (smem free after final __syncthreads; reuse sA for stats) ----
    const int Fsc = 1 << lgF;
    float* sSt = (float*)&sA[0][0][0];
    const int Fst = 1 << lgFstat;
    const bool doStats = (EMODE == 1) && (STp != nullptr);
    if (doStats) {
        for (int i = tid; i < 2 * Fst; i += 256) sSt[i] = 0.f;
        __syncthreads();
    }

    #pragma unroll
    for (int ni = 0; ni < 4; ni++) {
        int gc = col0 + n_w + ni * 8 + 2 * tg;
        float st0 = 0.f, st1 = 0.f, st2 = 0.f, st3 = 0.f;
        #pragma unroll
        for (int mi = 0; mi < 2; mi++) {
            const float* cp = acc[mi][ni];
            #pragma unroll
            for (int h = 0; h < 2; h++) {
                int r = row0 + m_w + mi * 16 + g + h * 8;
                if (r >= M) continue;
                float v0 = cp[2 * h], v1 = cp[2 * h + 1];
                if (EMODE == 2) {
                    if (gc < Nc)     atomicAdd(&Cf[r * ldc + gc], v0);
                    if (gc + 1 < Nc) atomicAdd(&Cf[r * ldc + gc + 1], v1);
                } else if (SCATTER) {
                    if (gc < Nc) {
                        int a = (gc >> lgF) * scPlane + r * Fsc + (gc & (Fsc - 1));
                        fsplit(v0, Ch[a], Cl[a]);
                    }
                    if (gc + 1 < Nc) {
                        int c1 = gc + 1;
                        int a = (c1 >> lgF) * scPlane + r * Fsc + (c1 & (Fsc - 1));
                        fsplit(v1, Ch[a], Cl[a]);
                    }
                } else {
                    if (gc < Nc) {   // Nc even in all dual uses
                        __nv_bfloat162 th, tl;
                        fsplit(v0, th.x, tl.x);
                        fsplit(v1, th.y, tl.y);
                        int o = r * ldc + gc;
                        *(__nv_bfloat162*)&Ch[o] = th;
                        *(__nv_bfloat162*)&Cl[o] = tl;
                    }
                }
                if (doStats) {
                    if (gc < Nc)     { st0 += v0; st1 += v0 * v0; }
                    if (gc + 1 < Nc) { st2 += v1; st3 += v1 * v1; }
                }
            }
        }
        if (doStats) {
            int f0 = gc & (Fst - 1), f1 = (gc + 1) & (Fst - 1);
            atomicAdd(&sSt[f0], st0);
            atomicAdd(&sSt[Fst + f0], st1);
            atomicAdd(&sSt[f1], st2);
            atomicAdd(&sSt[Fst + f1], st3);
        }
    }
    if (doStats) {
        __syncthreads();
        for (int i = tid; i < 2 * Fst; i += 256)
            if (sSt[i] != 0.f) atomicAdd(&STp[i], sSt[i]);
    }
}

// ---------------- fp32 SIMT GEMM (buildP only): C = alpha*A@B + beta*D ----------------
__global__ void __launch_bounds__(256)
gemm_f32k(int M, int Nc, int K,
          const float* __restrict__ A, int lda,
          const float* __restrict__ B, int ldb,
          float* __restrict__ C, int ldc,
          const float* __restrict__ D, float alpha, float beta)
{
    __shared__ float As[16][65];
    __shared__ float Bs[16][65];
    const int row0 = blockIdx.y << 6;
    const int col0 = blockIdx.x << 6;
    const int tid  = threadIdx.y * 16 + threadIdx.x;
    float acc[4][4] = {};
    for (int kt = 0; kt < K; kt += 16) {
        #pragma unroll
        for (int l = 0; l < 4; l++) {
            int e = tid + (l << 8);
            int m = e >> 4, kk = e & 15;
            int gr = row0 + m, gk = kt + kk;
            As[kk][m] = (gr < M && gk < K) ? A[gr * lda + gk] : 0.f;
        }
        #pragma unroll
        for (int l = 0; l < 4; l++) {
            int e = tid + (l << 8);
            int kk = e >> 6, n = e & 63;
            int gk = kt + kk, gc = col0 + n;
            Bs[kk][n] = (gk < K && gc < Nc) ? B[gk * ldb + gc] : 0.f;
        }
        __syncthreads();
        #pragma unroll
        for (int kk = 0; kk < 16; kk++) {
            float ra[4], rb[4];
            #pragma unroll
            for (int i = 0; i < 4; i++) ra[i] = As[kk][(threadIdx.y << 2) + i];
            #pragma unroll
            for (int j = 0; j < 4; j++) rb[j] = Bs[kk][(threadIdx.x << 2) + j];
            #pragma unroll
            for (int i = 0; i < 4; i++)
                #pragma unroll
                for (int j = 0; j < 4; j++)
                    acc[i][j] += ra[i] * rb[j];
        }
        __syncthreads();
    }
    #pragma unroll
    for (int i = 0; i < 4; i++) {
        int gr = row0 + (threadIdx.y << 2) + i;
        if (gr >= M) continue;
        #pragma unroll
        for (int j = 0; j < 4; j++) {
            int gc = col0 + (threadIdx.x << 2) + j;
            if (gc >= Nc) continue;
            float v = alpha * acc[i][j];
            if (D != nullptr) v += beta * D[gr * ldc + gc];
            C[gr * ldc + gc] = v;
        }
    }
}

// ---------------- small kernels ----------------
__global__ void zero_k(float* p, int n) {
    int i = blockIdx.x * blockDim.x + threadIdx.x;
    if (i < n) p[i] = 0.f;
}

__global__ void initP_k(float* __restrict__ P, const float* __restrict__ L, int N, int NN) {
    int i = blockIdx.x * blockDim.x + threadIdx.x;
    if (i >= 2 * NN) return;
    if (i < NN) P[i] = ((i / N) == (i % N)) ? 1.f : 0.f;
    else        P[i] = L[i - NN];
}

__global__ void split_k(const float* __restrict__ src, bf16* __restrict__ h,
                        bf16* __restrict__ l, int n) {
    int i = blockIdx.x * blockDim.x + threadIdx.x;
    if (i < n) fsplit(src[i], h[i], l[i]);
}

// PTd[(n*4+k)*N+m] = split(P[k][n][m])
__global__ void transP_split_k(const float* __restrict__ P, bf16* __restrict__ h,
                               bf16* __restrict__ l, int N, int NN) {
    int i = blockIdx.x * blockDim.x + threadIdx.x;
    if (i >= 4 * NN) return;
    int k = i / NN, r = i - k * NN;
    int n = r / N,  m = r - n * N;
    int o = (n * 4 + k) * N + m;
    fsplit(P[i], h[o], l[o]);
}

// decoder weight cat: Wc[f][k*F+o] = w[k][f][o]   (w is (4,Fin,F))
__global__ void wcat_split_k(const float* __restrict__ w, bf16* __restrict__ h,
                             bf16* __restrict__ l, int Fin, int F) {
    int tot = 4 * Fin * F;
    int i = blockIdx.x * blockDim.x + threadIdx.x;
    if (i >= tot) return;
    int k = i / (Fin * F), r = i - k * Fin * F;
    int f = r / F, o = r - f * F;
    int d = f * 4 * F + k * F + o;
    fsplit(w[i], h[d], l[d]);
}

// x (4,8,64,768) -> X dual (768, 256, 8)
__global__ void permute_in_split_k(const float* __restrict__ x, bf16* __restrict__ h,
                                   bf16* __restrict__ l) {
    int i = blockIdx.x * blockDim.x + threadIdx.x;
    if (i >= 768 * 256 * 8) return;
    int n = i >> 11;
    int rem = i & 2047;
    int bb = rem >> 3;
    int c  = rem & 7;
    int b  = bb >> 6, hw = bb & 63;
    fsplit(x[(((b * 8 + c) * 64) + hw) * 768 + n], h[i], l[i]);
}

__global__ void permute_out_k(const float* __restrict__ Fm, float* __restrict__ out) {
    int i = blockIdx.x * blockDim.x + threadIdx.x;
    if (i >= 196608) return;
    int bb = i / 768, n = i - bb * 768;
    out[i] = Fm[n * 256 + bb];
}

// fused BN(+ReLU) apply + full-res skip store + healpix 4:1 max pool
// Y raw (4Np,BB,F) -> S (BN'd, full) and D (BN'd, pooled)
__global__ void bn_pool_k(const bf16* __restrict__ Yh, const bf16* __restrict__ Yl,
                          bf16* __restrict__ Sh_, bf16* __restrict__ Sl_,
                          bf16* __restrict__ dh, bf16* __restrict__ dl,
                          int Np, int F, int R, const float* __restrict__ ST,
                          const float* __restrict__ g, const float* __restrict__ b) {
    int i = blockIdx.x * blockDim.x + threadIdx.x;
    int rowsz = BB * F;
    int tot = Np * rowsz;
    if (i >= tot) return;
    int n4 = i / rowsz, rem = i - n4 * rowsz;
    int f = rem & (F - 1);
    float m = (float)R;
    float mu = ST[f] / m;
    float var = ST[F + f] / m - mu * mu;
    float sc = rsqrtf(var + 1e-5f) * g[f];
    float sh = b[f] - mu * sc;
    int base = 4 * n4 * rowsz + rem;
    float best = -1.f;   // post-relu values are >= 0
    #pragma unroll
    for (int j = 0; j < 4; j++) {
        int o = base + j * rowsz;
        float v = dread(Yh, Yl, o) * sc + sh;
        v = v > 0.f ? v : 0.f;
        fsplit(v, Sh_[o], Sl_[o]);
        best = v > best ? v : best;
    }
    fsplit(best, dh[i], dl[i]);
}

// fused concat with BN(+ReLU) applied to the unpooled H half
// dst (N,BB,Fa+Fb) = concat(unpool(BNrelu(Hraw (N/4,BB,Fa))), S (N,BB,Fb))
__global__ void concat_bn_k(const bf16* __restrict__ Hh, const bf16* __restrict__ Hl,
                            const bf16* __restrict__ Sh_, const bf16* __restrict__ Sl_,
                            bf16* __restrict__ dh, bf16* __restrict__ dl,
                            int N, int Fa, int Fb, int R,
                            const float* __restrict__ ST,
                            const float* __restrict__ g, const float* __restrict__ b) {
    int Ft = Fa + Fb;
    int i = blockIdx.x * blockDim.x + threadIdx.x;
    int tot = N * BB * Ft;
    if (i >= tot) return;
    int n = i / (BB * Ft);
    int rem = i - n * (BB * Ft);
    int bb = rem / Ft;
    int f  = rem - bb * Ft;
    if (f < Fa) {
        int s = ((n >> 2) * BB + bb) * Fa + f;
        float m = (float)R;
        float mu = ST[f] / m;
        float var = ST[Fa + f] / m - mu * mu;
        float v = (dread(Hh, Hl, s) - mu) * rsqrtf(var + 1e-5f) * g[f] + b[f];
        v = v > 0.f ? v : 0.f;
        fsplit(v, dh[i], dl[i]);
    } else {
        int s = (n * BB + bb) * Fb + (f - Fa);
        dh[i] = Sh_[s]; dl[i] = Sl_[s];
    }
}

__global__ void bn_apply_k(const bf16* __restrict__ sh, const bf16* __restrict__ sl,
                           bf16* __restrict__ dh, bf16* __restrict__ dl,
                           int R, int F, const float* __restrict__ ST,
                           const float* __restrict__ g, const float* __restrict__ b) {
    int i = blockIdx.x * blockDim.x + threadIdx.x;
    int tot = R * F;
    if (i >= tot) return;
    int f = i % F;
    float m = (float)R;
    float mu = ST[f] / m;
    float var = ST[F + f] / m - mu * mu;
    float v = (dread(sh, sl, i) - mu) * rsqrtf(var + 1e-5f) * g[f] + b[f];
    v = v > 0.f ? v : 0.f;
    fsplit(v, dh[i], dl[i]);
}

// ---------------- host helpers ----------------
template<typename T> static void* symv(T& s) {
    void* p = nullptr;
    cudaGetSymbolAddress(&p, s);
    return p;
}

static int ilog2(int v) { int l = 0; while ((1 << l) < v) l++; return l; }

static void gemm_f32(int M, int Nc, int K, const float* A, int lda, const float* B, int ldb,
                     float* C, int ldc, const float* D, float alpha, float beta) {
    dim3 g((Nc + 63) / 64, (M + 63) / 64, 1), b(16, 16);
    gemm_f32k<<<g, b>>>(M, Nc, K, A, lda, B, ldb, C, ldc, D, alpha, beta);
}

static void gtc_dual(int M, int Nc, int K, const bf16* Ah, const bf16* Al, int lda,
                     const bf16* Bh, const bf16* Bl, int ldb,
                     bf16* Ch, bf16* Cl, int ldc,
                     float* ST = nullptr, int lgFstat = 0) {
    dim3 g((Nc + 63) / 64, (M + 127) / 128, 1);
    gemm_tc3<0, 1, false><<<g, 256>>>(M, Nc, K, Ah, Al, lda, Bh, Bl, ldb,
                                      Ch, Cl, nullptr, ldc, 0, 0, 0, 0, 0, ST, lgFstat);
}

static void gtc_gather(int M, int Nc, int Fin, const bf16* Ah, const bf16* Al, int strideK,
                       const bf16* Bh, const bf16* Bl, bf16* Ch, bf16* Cl,
                       float* ST = nullptr, int lgFstat = 0) {
    int K = 4 * Fin;
    dim3 g((Nc + 63) / 64, (M + 127) / 128, 1);
    gemm_tc3<1, 1, false><<<g, 256>>>(M, Nc, K, Ah, Al, 0, Bh, Bl, Nc,
                                      Ch, Cl, nullptr, Nc, Fin, ilog2(Fin), strideK, 0, 0,
                                      ST, lgFstat);
}

static void gtc_scatter(int M, int Nc, int K, const bf16* Ah, const bf16* Al, int lda,
                        const bf16* Bh, const bf16* Bl, int ldb,
                        bf16* Ch, bf16* Cl, int lgF, int scPlane) {
    dim3 g((Nc + 63) / 64, (M + 127) / 128, 1);
    gemm_tc3<0, 1, true><<<g, 256>>>(M, Nc, K, Ah, Al, lda, Bh, Bl, ldb,
                                     Ch, Cl, nullptr, 0, 0, 0, 0, lgF, scPlane, nullptr, 0);
}

static void gtc_splitk(int M, int Nc, int K, const bf16* Ah, const bf16* Al, int lda,
                       const bf16* Bh, const bf16* Bl, int ldb,
                       float* Cf, int ldc, int slices) {
    dim3 g((Nc + 63) / 64, (M + 127) / 128, slices);
    gemm_tc3<0, 2, false><<<g, 256>>>(M, Nc, K, Ah, Al, lda, Bh, Bl, ldb,
                                      nullptr, nullptr, Cf, ldc, 0, 0, 0, 0, 0, nullptr, 0);
}

static void buildP(const float* L, int N, float* P) {
    int NN = N * N;
    initP_k<<<(2 * NN + 255) / 256, 256>>>(P, L, N, NN);
    gemm_f32(N, N, N, L, N, P + NN,     N, P + 2 * NN, N, P,      2.f, -1.f);
    gemm_f32(N, N, N, L, N, P + 2 * NN, N, P + 3 * NN, N, P + NN, 2.f, -1.f);
}

// ---------------- entry point ----------------
extern "C" void kernel_launch(void* const* d_in, const int* in_sizes, int n_in,
                              void* d_out, int out_size) {
    const float* x     = (const float*)d_in[0];
    const float* L3i   = (const float*)d_in[1];
    const float* L2i   = (const float*)d_in[2];
    const float* L1i   = (const float*)d_in[3];
    const float* L0i   = (const float*)d_in[4];
    const float* w_e3a = (const float*)d_in[5];
    const float* ga_e3a= (const float*)d_in[6];
    const float* be_e3a= (const float*)d_in[7];
    const float* w_e3b = (const float*)d_in[8];
    const float* ga_e3b= (const float*)d_in[9];
    const float* be_e3b= (const float*)d_in[10];
    const float* w_e2  = (const float*)d_in[11];
    const float* ga_e2 = (const float*)d_in[12];
    const float* be_e2 = (const float*)d_in[13];
    const float* w_e1  = (const float*)d_in[14];
    const float* ga_e1 = (const float*)d_in[15];
    const float* be_e1 = (const float*)d_in[16];
    const float* w_e0  = (const float*)d_in[17];
    const float* ga_e0 = (const float*)d_in[18];
    const float* be_e0 = (const float*)d_in[19];
    const float* w_d1  = (const float*)d_in[20];
    const float* ga_d1 = (const float*)d_in[21];
    const float* be_d1 = (const float*)d_in[22];
    const float* w_d2  = (const float*)d_in[23];
    const float* ga_d2 = (const float*)d_in[24];
    const float* be_d2 = (const float*)d_in[25];
    const float* w_d3  = (const float*)d_in[26];
    const float* ga_d3 = (const float*)d_in[27];
    const float* be_d3 = (const float*)d_in[28];
    const float* w_out = (const float*)d_in[29];
    float* out = (float*)d_out;

    bf16 *Xh=(bf16*)symv(g_Xh), *Xl=(bf16*)symv(g_Xl);
    bf16 *Uh=(bf16*)symv(g_Uh), *Ul=(bf16*)symv(g_Ul);
    bf16 *Yh=(bf16*)symv(g_Yh), *Yl=(bf16*)symv(g_Yl);
    bf16 *S3h=(bf16*)symv(g_S3h), *S3l=(bf16*)symv(g_S3l);
    bf16 *S2h=(bf16*)symv(g_S2h), *S2l=(bf16*)symv(g_S2l);
    bf16 *S1h=(bf16*)symv(g_S1h), *S1l=(bf16*)symv(g_S1l);
    bf16 *Wh=(bf16*)symv(g_Wh), *Wl=(bf16*)symv(g_Wl);
    bf16 *P3h=(bf16*)symv(g_P3dh), *P3l=(bf16*)symv(g_P3dl);
    bf16 *PT3h=(bf16*)symv(g_PT3dh), *PT3l=(bf16*)symv(g_PT3dl);
    bf16 *P2h=(bf16*)symv(g_P2dh), *P2l=(bf16*)symv(g_P2dl);
    bf16 *PT2h=(bf16*)symv(g_PT2dh), *PT2l=(bf16*)symv(g_PT2dl);
    bf16 *P1h=(bf16*)symv(g_P1dh), *P1l=(bf16*)symv(g_P1dl);
    bf16 *PT1h=(bf16*)symv(g_PT1dh), *PT1l=(bf16*)symv(g_PT1dl);
    bf16 *P0h=(bf16*)symv(g_P0dh), *P0l=(bf16*)symv(g_P0dl);
    float *P3=(float*)symv(g_P3), *P2=(float*)symv(g_P2);
    float *P1=(float*)symv(g_P1), *P0=(float*)symv(g_P0);
    float *Fo=(float*)symv(g_F), *ST=(float*)symv(g_ST);

    // ---- P3 + first layer ----
    buildP(L3i, 768, P3);
    split_k<<<(2359296 + 255) / 256, 256>>>(P3, P3h, P3l, 2359296);
    permute_in_split_k<<<(768 * 256 * 8 + 255) / 256, 256>>>(x, Xh, Xl);

    // e3a: U = P3stack @ X ; Y = gather(U) @ w  (stats fused in gather epilogue)
    gtc_dual(4 * 768, BB * 8, 768, P3h, P3l, 768, Xh, Xl, BB * 8, Uh, Ul, BB * 8);
    split_k<<<(4 * 8 * 32 + 255) / 256, 256>>>(w_e3a, Wh, Wl, 4 * 8 * 32);
    zero_k<<<1, 512>>>(ST, 64);
    gtc_gather(768 * BB, 32, 8, Uh, Ul, 768 * BB * 8, Wh, Wl, Yh, Yl, ST, 5);
    bn_apply_k<<<(768 * BB * 32 + 255) / 256, 256>>>(Yh, Yl, Xh, Xl,
                                                     768 * BB, 32, ST, ga_e3a, be_e3a);

    // remaining P builds + transposed duals
    transP_split_k<<<(2359296 + 255) / 256, 256>>>(P3, PT3h, PT3l, 768, 589824);
    buildP(L2i, 192, P2);
    split_k<<<(147456 + 255) / 256, 256>>>(P2, P2h, P2l, 147456);
    transP_split_k<<<(147456 + 255) / 256, 256>>>(P2, PT2h, PT2l, 192, 36864);
    buildP(L1i, 48, P1);
    split_k<<<(9216 + 255) / 256, 256>>>(P1, P1h, P1l, 9216);
    transP_split_k<<<(9216 + 255) / 256, 256>>>(P1, PT1h, PT1l, 48, 2304);
    buildP(L0i, 12, P0);
    split_k<<<(576 + 255) / 256, 256>>>(P0, P0h, P0l, 576);

    // ---- e3b ----
    gtc_dual(4 * 768, BB * 32, 768, P3h, P3l, 768, Xh, Xl, BB * 32, Uh, Ul, BB * 32);
    split_k<<<(4 * 32 * 64 + 255) / 256, 256>>>(w_e3b, Wh, Wl, 4 * 32 * 64);
    zero_k<<<1, 512>>>(ST, 128);
    gtc_gather(768 * BB, 64, 32, Uh, Ul, 768 * BB * 32, Wh, Wl, Yh, Yl, ST, 6);
    bn_pool_k<<<(192 * BB * 64 + 255) / 256, 256>>>(Yh, Yl, S3h, S3l, Xh, Xl,
                                                    192, 64, 768 * BB, ST, ga_e3b, be_e3b);

    // ---- e2 ----
    gtc_dual(4 * 192, BB * 64, 192, P2h, P2l, 192, Xh, Xl, BB * 64, Uh, Ul, BB * 64);
    split_k<<<(4 * 64 * 128 + 255) / 256, 256>>>(w_e2, Wh, Wl, 4 * 64 * 128);
    zero_k<<<1, 512>>>(ST, 256);
    gtc_gather(192 * BB, 128, 64, Uh, Ul, 192 * BB * 64, Wh, Wl, Yh, Yl, ST, 7);
    bn_pool_k<<<(48 * BB * 128 + 255) / 256, 256>>>(Yh, Yl, S2h, S2l, Xh, Xl,
                                                    48, 128, 192 * BB, ST, ga_e2, be_e2);

    // ---- e1 ----
    gtc_dual(4 * 48, BB * 128, 48, P1h, P1l, 48, Xh, Xl, BB * 128, Uh, Ul, BB * 128);
    split_k<<<(4 * 128 * 256 + 255) / 256, 256>>>(w_e1, Wh, Wl, 4 * 128 * 256);
    zero_k<<<1, 512>>>(ST, 512);
    gtc_gather(48 * BB, 256, 128, Uh, Ul, 48 * BB * 128, Wh, Wl, Yh, Yl, ST, 8);
    bn_pool_k<<<(12 * BB * 256 + 255) / 256, 256>>>(Yh, Yl, S1h, S1l, Xh, Xl,
                                                    12, 256, 48 * BB, ST, ga_e1, be_e1);

    // ---- e0 ----  (lda=12 takes the scalar A path via avec guard)
    gtc_dual(4 * 12, BB * 256, 12, P0h, P0l, 12, Xh, Xl, BB * 256, Uh, Ul, BB * 256);
    split_k<<<(4 * 256 * 256 + 255) / 256, 256>>>(w_e0, Wh, Wl, 4 * 256 * 256);
    zero_k<<<1, 512>>>(ST, 512);
    gtc_gather(12 * BB, 256, 256, Uh, Ul, 12 * BB * 256, Wh, Wl, Yh, Yl, ST, 8);

    // ---- d1 ----  (BN of e0 fused into concat)
    concat_bn_k<<<(48 * BB * 512 + 255) / 256, 256>>>(Yh, Yl, S1h, S1l, Xh, Xl,
                                                      48, 256, 256, 12 * BB,
                                                      ST, ga_e0, be_e0);
    wcat_split_k<<<(4 * 512 * 128 + 255) / 256, 256>>>(w_d1, Wh, Wl, 512, 128);
    gtc_scatter(48 * BB, 4 * 128, 512, Xh, Xl, 512, Wh, Wl, 4 * 128,
                Uh, Ul, 7, 48 * BB * 128);
    zero_k<<<1, 512>>>(ST, 256);
    gtc_dual(48, BB * 128, 4 * 48, PT1h, PT1l, 4 * 48, Uh, Ul, BB * 128,
             Yh, Yl, BB * 128, ST, 7);

    // ---- d2 ----  (BN of d1 fused into concat)
    concat_bn_k<<<(192 * BB * 256 + 255) / 256, 256>>>(Yh, Yl, S2h, S2l, Xh, Xl,
                                                       192, 128, 128, 48 * BB,
                                                       ST, ga_d1, be_d1);
    wcat_split_k<<<(4 * 256 * 64 + 255) / 256, 256>>>(w_d2, Wh, Wl, 256, 64);
    gtc_scatter(192 * BB, 4 * 64, 256, Xh, Xl, 256, Wh, Wl, 4 * 64,
                Uh, Ul, 6, 192 * BB * 64);
    zero_k<<<1, 512>>>(ST, 128);
    gtc_dual(192, BB * 64, 4 * 192, PT2h, PT2l, 4 * 192, Uh, Ul, BB * 64,
             Yh, Yl, BB * 64, ST, 6);

    // ---- d3 ----  (BN of d2 fused into concat)
    concat_bn_k<<<(768 * BB * 128 + 255) / 256, 256>>>(Yh, Yl, S3h, S3l, Xh, Xl,
                                                       768, 64, 64, 192 * BB,
                                                       ST, ga_d2, be_d2);
    wcat_split_k<<<(4 * 128 * 32 + 255) / 256, 256>>>(w_d3, Wh, Wl, 128, 32);
    gtc_scatter(768 * BB, 4 * 32, 128, Xh, Xl, 128, Wh, Wl, 4 * 32,
                Uh, Ul, 5, 768 * BB * 32);
    zero_k<<<1, 512>>>(ST, 64);
    gtc_dual(768, BB * 32, 4 * 768, PT3h, PT3l, 4 * 768, Uh, Ul, BB * 32,
             Yh, Yl, BB * 32, ST, 5);
    bn_apply_k<<<(768 * BB * 32 + 255) / 256, 256>>>(Yh, Yl, Yh, Yl,
                                                     768 * BB, 32, ST, ga_d3, be_d3);

    // ---- out layer ----
    wcat_split_k<<<(4 * 32 + 255) / 256, 256>>>(w_out, Wh, Wl, 32, 1);
    gtc_scatter(768 * BB, 4, 32, Yh, Yl, 32, Wh, Wl, 4, Uh, Ul, 0, 768 * BB);
    zero_k<<<(196608 + 255) / 256, 256>>>(Fo, 196608);
    gtc_splitk(768, 256, 4 * 768, PT3h, PT3l, 4 * 768, Uh, Ul, 256, Fo, 256, 8);
    permute_out_k<<<(196608 + 255) / 256, 256>>>(Fo, out);
}